// round 2
// baseline (speedup 1.0000x reference)
#include <cuda_runtime.h>
#include <math.h>

// Problem constants
#define BB 8
#define SS 1024
#define EE 768
#define HH 12
#define DD 64

// Scratch (allocation-free rule: __device__ globals)
__device__ float g_q[(size_t)BB * HH * SS * DD];
__device__ float g_k[(size_t)BB * HH * SS * DD];
__device__ float g_v[(size_t)BB * HH * SS * DD];
__device__ float g_ctx[(size_t)BB * SS * EE];
__device__ int   g_len[BB];

// ---------------------------------------------------------------------------
// Mask -> per-batch valid length. Dtype-agnostic: detect 1-byte vs 4-byte
// elements via byte[1] (lengths >= S/2 guarantees element[1] is "true").
// Mask is a monotone prefix, so nonzero count == length.
// ---------------------------------------------------------------------------
__global__ void lengths_kernel(const unsigned char* __restrict__ mask)
{
    const int b = blockIdx.x;
    const int lane = threadIdx.x;
    int cnt = 0;
    if (mask[1] != 0) {
        // 1-byte elements (bool/int8)
        const unsigned char* row = mask + (size_t)b * SS;
        for (int i = lane; i < SS; i += 32) cnt += (row[i] != 0);
    } else {
        // 4-byte elements (int32/float32)
        const unsigned int* row = (const unsigned int*)mask + (size_t)b * SS;
        for (int i = lane; i < SS; i += 32) cnt += (row[i] != 0u);
    }
#pragma unroll
    for (int o = 16; o; o >>= 1) cnt += __shfl_xor_sync(0xffffffffu, cnt, o);
    if (lane == 0) g_len[b] = cnt;
}

// ---------------------------------------------------------------------------
// SGEMM: C[m,n] = sum_k A[m,k] * W[n,k] + bias[n]
// Both operands K-major (row-major A [M,K], row-major W [N,K]).
// 128x128 tile, BK=8, 256 threads, 8x8 per thread, double-buffered smem.
// MODE 0: scatter into q/k/v ([B,H,S,D]).   MODE 1: write C [M,768].
// ---------------------------------------------------------------------------
template <int MODE>
__global__ __launch_bounds__(256)
void gemm_kernel(const float* __restrict__ A, const float* __restrict__ W,
                 const float* __restrict__ bias, float* __restrict__ C,
                 float* __restrict__ Qo, float* __restrict__ Ko,
                 float* __restrict__ Vo, int K)
{
    __shared__ float As[2][8][128];
    __shared__ float Ws[2][8][128];

    const int tid  = threadIdx.x;
    const int m0   = blockIdx.y * 128;
    const int n0   = blockIdx.x * 128;
    const int lrow = tid >> 1;
    const int lseg = (tid & 1) << 2;
    const int tx   = tid & 15;
    const int ty   = tid >> 4;

    const float* Ap = A + (size_t)(m0 + lrow) * K + lseg;
    const float* Wp = W + (size_t)(n0 + lrow) * K + lseg;

    float acc[8][8];
#pragma unroll
    for (int i = 0; i < 8; ++i)
#pragma unroll
        for (int j = 0; j < 8; ++j) acc[i][j] = 0.f;

    // prologue: tile 0 -> buffer 0
    {
        float4 a4 = *(const float4*)Ap;
        float4 w4 = *(const float4*)Wp;
        As[0][lseg + 0][lrow] = a4.x; As[0][lseg + 1][lrow] = a4.y;
        As[0][lseg + 2][lrow] = a4.z; As[0][lseg + 3][lrow] = a4.w;
        Ws[0][lseg + 0][lrow] = w4.x; Ws[0][lseg + 1][lrow] = w4.y;
        Ws[0][lseg + 2][lrow] = w4.z; Ws[0][lseg + 3][lrow] = w4.w;
    }
    __syncthreads();

    const int nT = K >> 3;
    for (int t = 0; t < nT; ++t) {
        const int cur = t & 1;
        float4 a4n, w4n;
        if (t + 1 < nT) {
            a4n = *(const float4*)(Ap + (t + 1) * 8);
            w4n = *(const float4*)(Wp + (t + 1) * 8);
        }
#pragma unroll
        for (int kk = 0; kk < 8; ++kk) {
            float ar[8], wr[8];
            *(float4*)(ar)     = *(const float4*)&As[cur][kk][ty * 8];
            *(float4*)(ar + 4) = *(const float4*)&As[cur][kk][ty * 8 + 4];
            *(float4*)(wr)     = *(const float4*)&Ws[cur][kk][tx * 8];
            *(float4*)(wr + 4) = *(const float4*)&Ws[cur][kk][tx * 8 + 4];
#pragma unroll
            for (int i = 0; i < 8; ++i)
#pragma unroll
                for (int j = 0; j < 8; ++j)
                    acc[i][j] += ar[i] * wr[j];
        }
        if (t + 1 < nT) {
            const int nxt = cur ^ 1;
            As[nxt][lseg + 0][lrow] = a4n.x; As[nxt][lseg + 1][lrow] = a4n.y;
            As[nxt][lseg + 2][lrow] = a4n.z; As[nxt][lseg + 3][lrow] = a4n.w;
            Ws[nxt][lseg + 0][lrow] = w4n.x; Ws[nxt][lseg + 1][lrow] = w4n.y;
            Ws[nxt][lseg + 2][lrow] = w4n.z; Ws[nxt][lseg + 3][lrow] = w4n.w;
            __syncthreads();
        }
    }

#pragma unroll
    for (int i = 0; i < 8; ++i) {
        const int m = m0 + ty * 8 + i;
#pragma unroll
        for (int j = 0; j < 8; ++j) {
            const int n = n0 + tx * 8 + j;
            const float val = acc[i][j] + bias[n];
            if (MODE == 0) {
                const int c = n / EE;         // 0=q, 1=k, 2=v
                const int r = n - c * EE;
                const int h = r >> 6;
                const int d = r & 63;
                const int b = m >> 10;
                const int s = m & 1023;
                float* dst = (c == 0) ? Qo : (c == 1) ? Ko : Vo;
                dst[(((size_t)b * HH + h) * SS + s) * DD + d] = val;
            } else {
                C[(size_t)m * EE + n] = val;
            }
        }
    }
}

// ---------------------------------------------------------------------------
// Flash attention, fp32. One query row per thread (128 q rows per CTA),
// K/V tiles of 64 keys staged in smem, raw scores staged in smem (Ps)
// so the tile max is known before exponentiation.
// Dynamic smem: Ks 16KB | Vs 16KB | Ps 32KB = 64KB.
// ---------------------------------------------------------------------------
__global__ __launch_bounds__(128)
void attn_kernel(const float* __restrict__ q, const float* __restrict__ k,
                 const float* __restrict__ v, float* __restrict__ ctx)
{
    extern __shared__ float smem[];
    float4* Ks4 = (float4*)smem;                 // [64][16] float4
    float4* Vs4 = (float4*)(smem + 4096);        // [64][16] float4
    float*  Ps  = smem + 8192;                   // [64][128]

    const int tid = threadIdx.x;
    const int hh  = blockIdx.y;
    const int bb  = blockIdx.z;
    const int bh  = bb * HH + hh;
    const int s   = blockIdx.x * 128 + tid;
    const int len = g_len[bb];

    float4 qr[16];
    {
        const float4* qg = (const float4*)(q + ((size_t)bh * SS + s) * DD);
#pragma unroll
        for (int i = 0; i < 16; ++i) qr[i] = qg[i];
    }

    float4 o4[16];
#pragma unroll
    for (int i = 0; i < 16; ++i) o4[i] = make_float4(0.f, 0.f, 0.f, 0.f);
    float m = -1e30f, l = 0.f;

    const float4* kg = (const float4*)(k + (size_t)bh * SS * DD);
    const float4* vg = (const float4*)(v + (size_t)bh * SS * DD);

    for (int j0 = 0; j0 < len; j0 += 64) {
        __syncthreads();   // previous tile fully consumed
#pragma unroll
        for (int i = 0; i < 8; ++i) {
            const int idx = tid + 128 * i;       // = j*16 + seg
            Ks4[idx] = kg[j0 * 16 + idx];
            Vs4[idx] = vg[j0 * 16 + idx];
        }
        __syncthreads();

        const int nk = min(64, len - j0);

        // pass 1: raw scores + tile max
        float mt = -1e30f;
        for (int j = 0; j < nk; ++j) {
            const float4* kr = &Ks4[j * 16];
            float4 acc = make_float4(0.f, 0.f, 0.f, 0.f);
#pragma unroll
            for (int i = 0; i < 16; ++i) {
                const float4 kv = kr[i];
                acc.x += qr[i].x * kv.x;
                acc.y += qr[i].y * kv.y;
                acc.z += qr[i].z * kv.z;
                acc.w += qr[i].w * kv.w;
            }
            const float sc = (acc.x + acc.y + acc.z + acc.w) * 0.125f;
            Ps[j * 128 + tid] = sc;
            mt = fmaxf(mt, sc);
        }

        // rescale running state
        const float mnew = fmaxf(m, mt);
        const float corr = __expf(m - mnew);
        l *= corr;
#pragma unroll
        for (int i = 0; i < 16; ++i) {
            o4[i].x *= corr; o4[i].y *= corr;
            o4[i].z *= corr; o4[i].w *= corr;
        }
        m = mnew;

        // pass 2: exp + accumulate P@V
        for (int j = 0; j < nk; ++j) {
            const float p = __expf(Ps[j * 128 + tid] - m);
            l += p;
            const float4* vr = &Vs4[j * 16];
#pragma unroll
            for (int i = 0; i < 16; ++i) {
                const float4 vv = vr[i];
                o4[i].x += p * vv.x;
                o4[i].y += p * vv.y;
                o4[i].z += p * vv.z;
                o4[i].w += p * vv.w;
            }
        }
    }

    const float fin = (s < len) ? (1.0f / l) : 0.f;   // zero padded query rows
    float4* og = (float4*)(ctx + ((size_t)bb * SS + s) * EE + hh * DD);
#pragma unroll
    for (int i = 0; i < 16; ++i) {
        float4 t = o4[i];
        t.x *= fin; t.y *= fin; t.z *= fin; t.w *= fin;
        og[i] = t;
    }
}

// ---------------------------------------------------------------------------
// Launch
// ---------------------------------------------------------------------------
extern "C" void kernel_launch(void* const* d_in, const int* in_sizes, int n_in,
                              void* d_out, int out_size)
{
    const float* x               = (const float*)d_in[0];
    const unsigned char* mask    = (const unsigned char*)d_in[1];
    const float* Wqkv_w          = (const float*)d_in[2];
    const float* Wqkv_b          = (const float*)d_in[3];
    const float* out_w           = (const float*)d_in[4];
    const float* out_b           = (const float*)d_in[5];
    float* out                   = (float*)d_out;

    float *qp, *kp, *vp, *cp;
    cudaGetSymbolAddress((void**)&qp, g_q);
    cudaGetSymbolAddress((void**)&kp, g_k);
    cudaGetSymbolAddress((void**)&vp, g_v);
    cudaGetSymbolAddress((void**)&cp, g_ctx);

    // 1) per-batch lengths from the padding mask
    lengths_kernel<<<BB, 32>>>(mask);

    // 2) QKV projection: [8192,768] @ [2304,768]^T -> scatter q/k/v [B,H,S,D]
    {
        dim3 grid(3 * EE / 128, (BB * SS) / 128);
        gemm_kernel<0><<<grid, 256>>>(x, Wqkv_w, Wqkv_b, nullptr, qp, kp, vp, EE);
    }

    // 3) flash attention -> ctx [B,S,E]
    cudaFuncSetAttribute(attn_kernel, cudaFuncAttributeMaxDynamicSharedMemorySize, 65536);
    attn_kernel<<<dim3(SS / 128, HH, BB), 128, 65536>>>(qp, kp, vp, cp);

    // 4) output projection: [8192,768] @ [768,768]^T + bias -> out
    {
        dim3 grid(EE / 128, (BB * SS) / 128);
        gemm_kernel<1><<<grid, 256>>>(cp, out_w, out_b, out, nullptr, nullptr, nullptr, EE);
    }
}

// round 4
// speedup vs baseline: 1.3055x; 1.3055x over previous
#include <cuda_runtime.h>
#include <math.h>
#include <stdint.h>
#include <mma.h>

using namespace nvcuda;

// Problem constants
#define BB 8
#define SS 1024
#define EE 768
#define HH 12
#define DD 64

// GEMM tiling
#define BM 128
#define BN 128
#define BKK 32
#define LDS_K 36          // padded K-stride in smem (floats)
#define LDS_C 132         // padded N-stride for epilogue tile

// Scratch (allocation-free rule: __device__ globals)
__device__ float g_q[(size_t)BB * HH * SS * DD];
__device__ float g_k[(size_t)BB * HH * SS * DD];
__device__ float g_v[(size_t)BB * HH * SS * DD];
__device__ float g_ctx[(size_t)BB * SS * EE];
__device__ int   g_len[BB];

__device__ __forceinline__ float totf32(float x) {
    float y;
    asm("cvt.rna.tf32.f32 %0, %1;" : "=f"(y) : "f"(x));
    return y;
}

// ---------------------------------------------------------------------------
// Mask -> per-batch valid length (prefix mask; count nonzeros).
// ---------------------------------------------------------------------------
__global__ void lengths_kernel(const unsigned char* __restrict__ mask)
{
    const int b = blockIdx.x;
    const int lane = threadIdx.x;
    int cnt = 0;
    if (mask[1] != 0) {
        const unsigned char* row = mask + (size_t)b * SS;
        for (int i = lane; i < SS; i += 32) cnt += (row[i] != 0);
    } else {
        const unsigned int* row = (const unsigned int*)mask + (size_t)b * SS;
        for (int i = lane; i < SS; i += 32) cnt += (row[i] != 0u);
    }
#pragma unroll
    for (int o = 16; o; o >>= 1) cnt += __shfl_xor_sync(0xffffffffu, cnt, o);
    if (lane == 0) g_len[b] = cnt;
}

// ---------------------------------------------------------------------------
// Tensor-core (wmma tf32) GEMM: C[m,n] = sum_k A[m,k]*W[n,k] + bias[n]
// A: [M,768] row-major. W: [N,768] row-major (so B^T, i.e. col-major [K,N]).
// CTA tile 128x128, BK=32, 256 threads = 8 warps in 4(m) x 2(n) grid,
// warp tile 32x64: 2 m-frags x 4 n-frags of wmma 16x16x8 tf32.
// Double-buffered smem; tf32 rounding applied on the smem-fill path.
// MODE 0: scatter into q/k/v [B,H,S,D].  MODE 1: write C [M,768].
// ---------------------------------------------------------------------------
#define GEMM_SMEM_FLOATS (4 * BM * LDS_K)   // 2 bufs x (A + B) = 18432 floats
#define GEMM_SMEM_BYTES  (GEMM_SMEM_FLOATS * 4)

template <int MODE>
__global__ __launch_bounds__(256)
void tc_gemm(const float* __restrict__ A, const float* __restrict__ W,
             const float* __restrict__ bias, float* __restrict__ C,
             float* __restrict__ Qo, float* __restrict__ Ko, float* __restrict__ Vo)
{
    extern __shared__ float smem[];
    // layout: [buf0 A | buf0 B | buf1 A | buf1 B], each BM*LDS_K floats
    float* Cs = smem;   // epilogue tile aliases the buffers (after final sync)

    const int tid    = threadIdx.x;
    const int wid    = tid >> 5;
    const int warp_m = wid & 3;        // 0..3  (32-row slabs)
    const int warp_n = wid >> 2;       // 0..1  (64-col slabs)
    const int m0     = blockIdx.y * BM;
    const int n0     = blockIdx.x * BN;

    const float* Abase = A + (size_t)m0 * EE;
    const float* Wbase = W + (size_t)n0 * EE;

    wmma::fragment<wmma::accumulator, 16, 16, 8, float> acc[2][4];
#pragma unroll
    for (int i = 0; i < 2; ++i)
#pragma unroll
        for (int j = 0; j < 4; ++j) wmma::fill_fragment(acc[i][j], 0.0f);

    // load one 128x32 A tile + 128x32 W tile (tf32-rounded) into buffer `buf`
    auto load_chunk = [&](int t, int buf) {
        float* sA = smem + buf * (2 * BM * LDS_K);
        float* sB = sA + BM * LDS_K;
        const float* Ag = Abase + t * BKK;
        const float* Wg = Wbase + t * BKK;
#pragma unroll
        for (int i = 0; i < 4; ++i) {
            const int fi  = tid + (i << 8);     // 0..1023 float4 slots
            const int row = fi >> 3;            // 0..127
            const int seg = fi & 7;             // 0..7 (float4 within 32 K)
            float4 a = *(const float4*)(Ag + (size_t)row * EE + seg * 4);
            float4 w = *(const float4*)(Wg + (size_t)row * EE + seg * 4);
            a.x = totf32(a.x); a.y = totf32(a.y); a.z = totf32(a.z); a.w = totf32(a.w);
            w.x = totf32(w.x); w.y = totf32(w.y); w.z = totf32(w.z); w.w = totf32(w.w);
            *(float4*)(sA + row * LDS_K + seg * 4) = a;
            *(float4*)(sB + row * LDS_K + seg * 4) = w;
        }
    };

    load_chunk(0, 0);
    __syncthreads();

    const int nT = EE / BKK;   // 24
    for (int t = 0; t < nT; ++t) {
        const int cur = t & 1;
        float* sA = smem + cur * (2 * BM * LDS_K);
        float* sB = sA + BM * LDS_K;

        // prefetch next tile to registers happens implicitly via L1; load after compute
#pragma unroll
        for (int kk = 0; kk < BKK / 8; ++kk) {
            wmma::fragment<wmma::matrix_a, 16, 16, 8, wmma::precision::tf32, wmma::row_major> af[2];
            wmma::fragment<wmma::matrix_b, 16, 16, 8, wmma::precision::tf32, wmma::col_major> bf[4];
#pragma unroll
            for (int i = 0; i < 2; ++i)
                wmma::load_matrix_sync(af[i], sA + (warp_m * 32 + i * 16) * LDS_K + kk * 8, LDS_K);
#pragma unroll
            for (int j = 0; j < 4; ++j)
                wmma::load_matrix_sync(bf[j], sB + (warp_n * 64 + j * 16) * LDS_K + kk * 8, LDS_K);
#pragma unroll
            for (int i = 0; i < 2; ++i)
#pragma unroll
                for (int j = 0; j < 4; ++j)
                    wmma::mma_sync(acc[i][j], af[i], bf[j], acc[i][j]);
        }

        if (t + 1 < nT) {
            load_chunk(t + 1, cur ^ 1);
        }
        __syncthreads();
    }

    // epilogue: fragments -> smem tile -> bias add + (scatter | store)
#pragma unroll
    for (int i = 0; i < 2; ++i)
#pragma unroll
        for (int j = 0; j < 4; ++j)
            wmma::store_matrix_sync(Cs + (warp_m * 32 + i * 16) * LDS_C + warp_n * 64 + j * 16,
                                    acc[i][j], LDS_C, wmma::mem_row_major);
    __syncthreads();

#pragma unroll
    for (int i = 0; i < 16; ++i) {
        const int fi  = tid + (i << 8);    // 0..4095
        const int row = fi >> 5;           // 0..127
        const int col = (fi & 31) * 4;     // 0..124
        const int m = m0 + row;
        const int n = n0 + col;
        float4 o = *(const float4*)(Cs + row * LDS_C + col);
        const float4 bv = *(const float4*)(bias + n);
        o.x += bv.x; o.y += bv.y; o.z += bv.z; o.w += bv.w;
        if (MODE == 0) {
            const int c  = n / EE;          // 0=q,1=k,2=v
            const int rr = n - c * EE;
            const int h  = rr >> 6;
            const int d  = rr & 63;
            const int b  = m >> 10;
            const int s  = m & 1023;
            float* dst = (c == 0) ? Qo : (c == 1) ? Ko : Vo;
            *(float4*)(dst + ((((size_t)b * HH + h) * SS + s) * DD + d)) = o;
        } else {
            *(float4*)(C + (size_t)m * EE + n) = o;
        }
    }
}

// ---------------------------------------------------------------------------
// Flash attention, fp32 (unchanged; known correct).
// ---------------------------------------------------------------------------
__global__ __launch_bounds__(128)
void attn_kernel(const float* __restrict__ q, const float* __restrict__ k,
                 const float* __restrict__ v, float* __restrict__ ctx)
{
    extern __shared__ float smem[];
    float4* Ks4 = (float4*)smem;                 // [64][16] float4
    float4* Vs4 = (float4*)(smem + 4096);        // [64][16] float4
    float*  Ps  = smem + 8192;                   // [64][128]

    const int tid = threadIdx.x;
    const int hh  = blockIdx.y;
    const int bb  = blockIdx.z;
    const int bh  = bb * HH + hh;
    const int s   = blockIdx.x * 128 + tid;
    const int len = g_len[bb];

    float4 qr[16];
    {
        const float4* qg = (const float4*)(q + ((size_t)bh * SS + s) * DD);
#pragma unroll
        for (int i = 0; i < 16; ++i) qr[i] = qg[i];
    }

    float4 o4[16];
#pragma unroll
    for (int i = 0; i < 16; ++i) o4[i] = make_float4(0.f, 0.f, 0.f, 0.f);
    float m = -1e30f, l = 0.f;

    const float4* kg = (const float4*)(k + (size_t)bh * SS * DD);
    const float4* vg = (const float4*)(v + (size_t)bh * SS * DD);

    for (int j0 = 0; j0 < len; j0 += 64) {
        __syncthreads();
#pragma unroll
        for (int i = 0; i < 8; ++i) {
            const int idx = tid + 128 * i;
            Ks4[idx] = kg[j0 * 16 + idx];
            Vs4[idx] = vg[j0 * 16 + idx];
        }
        __syncthreads();

        const int nk = min(64, len - j0);

        float mt = -1e30f;
        for (int j = 0; j < nk; ++j) {
            const float4* kr = &Ks4[j * 16];
            float4 acc = make_float4(0.f, 0.f, 0.f, 0.f);
#pragma unroll
            for (int i = 0; i < 16; ++i) {
                const float4 kv = kr[i];
                acc.x += qr[i].x * kv.x;
                acc.y += qr[i].y * kv.y;
                acc.z += qr[i].z * kv.z;
                acc.w += qr[i].w * kv.w;
            }
            const float sc = (acc.x + acc.y + acc.z + acc.w) * 0.125f;
            Ps[j * 128 + tid] = sc;
            mt = fmaxf(mt, sc);
        }

        const float mnew = fmaxf(m, mt);
        const float corr = __expf(m - mnew);
        l *= corr;
#pragma unroll
        for (int i = 0; i < 16; ++i) {
            o4[i].x *= corr; o4[i].y *= corr;
            o4[i].z *= corr; o4[i].w *= corr;
        }
        m = mnew;

        for (int j = 0; j < nk; ++j) {
            const float p = __expf(Ps[j * 128 + tid] - m);
            l += p;
            const float4* vr = &Vs4[j * 16];
#pragma unroll
            for (int i = 0; i < 16; ++i) {
                const float4 vv = vr[i];
                o4[i].x += p * vv.x;
                o4[i].y += p * vv.y;
                o4[i].z += p * vv.z;
                o4[i].w += p * vv.w;
            }
        }
    }

    const float fin = (s < len) ? (1.0f / l) : 0.f;
    float4* og = (float4*)(ctx + ((size_t)bb * SS + s) * EE + hh * DD);
#pragma unroll
    for (int i = 0; i < 16; ++i) {
        float4 t = o4[i];
        t.x *= fin; t.y *= fin; t.z *= fin; t.w *= fin;
        og[i] = t;
    }
}

// ---------------------------------------------------------------------------
// Launch
// ---------------------------------------------------------------------------
extern "C" void kernel_launch(void* const* d_in, const int* in_sizes, int n_in,
                              void* d_out, int out_size)
{
    const float* x            = (const float*)d_in[0];
    const unsigned char* mask = (const unsigned char*)d_in[1];
    const float* Wqkv_w       = (const float*)d_in[2];
    const float* Wqkv_b       = (const float*)d_in[3];
    const float* out_w        = (const float*)d_in[4];
    const float* out_b        = (const float*)d_in[5];
    float* out                = (float*)d_out;

    float *qp, *kp, *vp, *cp;
    cudaGetSymbolAddress((void**)&qp, g_q);
    cudaGetSymbolAddress((void**)&kp, g_k);
    cudaGetSymbolAddress((void**)&vp, g_v);
    cudaGetSymbolAddress((void**)&cp, g_ctx);

    // 1) per-batch lengths
    lengths_kernel<<<BB, 32>>>(mask);

    // 2) QKV projection (wmma tf32): [8192,768]x[2304,768]^T -> q/k/v
    cudaFuncSetAttribute(tc_gemm<0>, cudaFuncAttributeMaxDynamicSharedMemorySize, GEMM_SMEM_BYTES);
    cudaFuncSetAttribute(tc_gemm<1>, cudaFuncAttributeMaxDynamicSharedMemorySize, GEMM_SMEM_BYTES);
    {
        dim3 grid(3 * EE / BN, (BB * SS) / BM);   // (18, 64)
        tc_gemm<0><<<grid, 256, GEMM_SMEM_BYTES>>>(x, Wqkv_w, Wqkv_b, nullptr, qp, kp, vp);
    }

    // 3) flash attention -> ctx [B,S,E]
    cudaFuncSetAttribute(attn_kernel, cudaFuncAttributeMaxDynamicSharedMemorySize, 65536);
    attn_kernel<<<dim3(SS / 128, HH, BB), 128, 65536>>>(qp, kp, vp, cp);

    // 4) output projection (wmma tf32): [8192,768]x[768,768]^T + bias -> out
    {
        dim3 grid(EE / BN, (BB * SS) / BM);       // (6, 64)
        tc_gemm<1><<<grid, 256, GEMM_SMEM_BYTES>>>(cp, out_w, out_b, out, nullptr, nullptr, nullptr);
    }
}

// round 5
// speedup vs baseline: 4.3868x; 3.3602x over previous
#include <cuda_runtime.h>
#include <cuda_fp16.h>
#include <math.h>
#include <stdint.h>
#include <mma.h>

using namespace nvcuda;

// Problem constants
#define BB 8
#define SS 1024
#define EE 768
#define HH 12
#define DD 64

// GEMM tiling
#define BM 128
#define BN 128
#define BK 64
#define LDH 72            // padded halves stride in smem tiles
#define LDS_C 132         // padded fp32 stride for epilogue tile

// Attention smem strides
#define ATT_LDH 72        // halves
#define ATT_LDF 68        // fp32

// Scratch (allocation-free rule: __device__ globals)
__device__ __half g_xh[(size_t)BB * SS * EE];
__device__ __half g_wqkvh[(size_t)3 * EE * EE];
__device__ __half g_owh[(size_t)EE * EE];
__device__ __half g_qh[(size_t)BB * HH * SS * DD];
__device__ __half g_kh[(size_t)BB * HH * SS * DD];
__device__ __half g_vh[(size_t)BB * HH * SS * DD];
__device__ __half g_ctxh[(size_t)BB * SS * EE];
__device__ int    g_len[BB];

// ---------------------------------------------------------------------------
// fp32 -> fp16 conversion (RN)
// ---------------------------------------------------------------------------
__global__ void conv_kernel(const float* __restrict__ src, __half* __restrict__ dst, int n4)
{
    const int i = blockIdx.x * 256 + threadIdx.x;
    if (i < n4) {
        const float4 v = ((const float4*)src)[i];
        __half2 h0 = __floats2half2_rn(v.x, v.y);
        __half2 h1 = __floats2half2_rn(v.z, v.w);
        ((__half2*)dst)[i * 2]     = h0;
        ((__half2*)dst)[i * 2 + 1] = h1;
    }
}

// ---------------------------------------------------------------------------
// Mask -> per-batch valid length (prefix mask; count nonzeros).
// ---------------------------------------------------------------------------
__global__ void lengths_kernel(const unsigned char* __restrict__ mask)
{
    const int b = blockIdx.x;
    const int lane = threadIdx.x;
    int cnt = 0;
    if (mask[1] != 0) {
        const unsigned char* row = mask + (size_t)b * SS;
        for (int i = lane; i < SS; i += 32) cnt += (row[i] != 0);
    } else {
        const unsigned int* row = (const unsigned int*)mask + (size_t)b * SS;
        for (int i = lane; i < SS; i += 32) cnt += (row[i] != 0u);
    }
#pragma unroll
    for (int o = 16; o; o >>= 1) cnt += __shfl_xor_sync(0xffffffffu, cnt, o);
    if (lane == 0) g_len[b] = cnt;
}

// ---------------------------------------------------------------------------
// fp16 wmma GEMM: C[m,n] = sum_k A[m,k]*W[n,k] + bias[n]
// A [M,768] fp16 row-major; W [N,768] fp16 row-major (acts as col-major B).
// CTA 128x128, BK=64, 256 threads (8 warps, 4m x 2n), warp tile 32x64.
// cp.async double-buffered smem. MODE 0: scatter q/k/v fp16 (q pre-scaled
// by 1/8). MODE 1: write fp32 C [M,768].
// ---------------------------------------------------------------------------
#define GEMM_SMEM_BYTES (2 * 2 * BM * LDH * 2)   // 2 bufs x (A+B) x 128x72 halves = 73728

template <int MODE>
__global__ __launch_bounds__(256, 2)
void tc_gemm(const __half* __restrict__ A, const __half* __restrict__ W,
             const float* __restrict__ bias, float* __restrict__ C,
             __half* __restrict__ Qo, __half* __restrict__ Ko, __half* __restrict__ Vo)
{
    extern __shared__ char smraw[];
    __half* sbuf = (__half*)smraw;
    float*  Cs   = (float*)smraw;      // epilogue alias (after final sync)

    const int tid    = threadIdx.x;
    const int wid    = tid >> 5;
    const int warp_m = wid & 3;
    const int warp_n = wid >> 2;
    const int m0     = blockIdx.y * BM;
    const int n0     = blockIdx.x * BN;

    const __half* Abase = A + (size_t)m0 * EE;
    const __half* Wbase = W + (size_t)n0 * EE;

    wmma::fragment<wmma::accumulator, 16, 16, 16, float> acc[2][4];
#pragma unroll
    for (int i = 0; i < 2; ++i)
#pragma unroll
        for (int j = 0; j < 4; ++j) wmma::fill_fragment(acc[i][j], 0.0f);

    // cp.async one 128x64 A tile + 128x64 B tile into buffer `buf`
    auto issue_tile = [&](int t, int buf) {
        const __half* Ag = Abase + t * BK;
        const __half* Wg = Wbase + t * BK;
        __half* sA = sbuf + buf * (2 * BM * LDH);
        __half* sB = sA + BM * LDH;
#pragma unroll
        for (int i = 0; i < 4; ++i) {
            const int idx = tid + (i << 8);        // 0..1023 16B chunks
            const int row = idx >> 3;
            const int seg = idx & 7;
            const __half* srcA = Ag + (size_t)row * EE + seg * 8;
            const __half* srcB = Wg + (size_t)row * EE + seg * 8;
            uint32_t dA = (uint32_t)__cvta_generic_to_shared(sA + row * LDH + seg * 8);
            uint32_t dB = (uint32_t)__cvta_generic_to_shared(sB + row * LDH + seg * 8);
            asm volatile("cp.async.cg.shared.global [%0], [%1], 16;" :: "r"(dA), "l"(srcA));
            asm volatile("cp.async.cg.shared.global [%0], [%1], 16;" :: "r"(dB), "l"(srcB));
        }
        asm volatile("cp.async.commit_group;" ::: "memory");
    };

    issue_tile(0, 0);

    const int nT = EE / BK;    // 12
    for (int t = 0; t < nT; ++t) {
        if (t + 1 < nT) {
            issue_tile(t + 1, (t + 1) & 1);
            asm volatile("cp.async.wait_group 1;" ::: "memory");
        } else {
            asm volatile("cp.async.wait_group 0;" ::: "memory");
        }
        __syncthreads();

        const __half* sA = sbuf + (t & 1) * (2 * BM * LDH);
        const __half* sB = sA + BM * LDH;
#pragma unroll
        for (int kk = 0; kk < BK / 16; ++kk) {
            wmma::fragment<wmma::matrix_a, 16, 16, 16, __half, wmma::row_major> af[2];
            wmma::fragment<wmma::matrix_b, 16, 16, 16, __half, wmma::col_major> bf[4];
#pragma unroll
            for (int i = 0; i < 2; ++i)
                wmma::load_matrix_sync(af[i], sA + (warp_m * 32 + i * 16) * LDH + kk * 16, LDH);
#pragma unroll
            for (int j = 0; j < 4; ++j)
                wmma::load_matrix_sync(bf[j], sB + (warp_n * 64 + j * 16) * LDH + kk * 16, LDH);
#pragma unroll
            for (int i = 0; i < 2; ++i)
#pragma unroll
                for (int j = 0; j < 4; ++j)
                    wmma::mma_sync(acc[i][j], af[i], bf[j], acc[i][j]);
        }
        __syncthreads();
    }

    // epilogue: fragments -> smem -> bias + store
#pragma unroll
    for (int i = 0; i < 2; ++i)
#pragma unroll
        for (int j = 0; j < 4; ++j)
            wmma::store_matrix_sync(Cs + (warp_m * 32 + i * 16) * LDS_C + warp_n * 64 + j * 16,
                                    acc[i][j], LDS_C, wmma::mem_row_major);
    __syncthreads();

#pragma unroll
    for (int i = 0; i < 16; ++i) {
        const int fi  = tid + (i << 8);
        const int row = fi >> 5;
        const int col = (fi & 31) * 4;
        const int m = m0 + row;
        const int n = n0 + col;
        float4 o = *(const float4*)(Cs + row * LDS_C + col);
        const float4 bv = *(const float4*)(bias + n);
        o.x += bv.x; o.y += bv.y; o.z += bv.z; o.w += bv.w;
        if (MODE == 0) {
            const int c  = n / EE;
            const int rr = n - c * EE;
            const int h  = rr >> 6;
            const int d  = rr & 63;
            const int b  = m >> 10;
            const int s  = m & 1023;
            if (c == 0) { o.x *= 0.125f; o.y *= 0.125f; o.z *= 0.125f; o.w *= 0.125f; }
            __half* dst = ((c == 0) ? Qo : (c == 1) ? Ko : Vo)
                          + ((((size_t)b * HH + h) * SS + s) * DD + d);
            __half2 h0 = __floats2half2_rn(o.x, o.y);
            __half2 h1 = __floats2half2_rn(o.z, o.w);
            *(__half2*)(dst)     = h0;
            *(__half2*)(dst + 2) = h1;
        } else {
            *(float4*)(C + (size_t)m * EE + n) = o;
        }
    }
}

// ---------------------------------------------------------------------------
// Tensor-core flash attention (fp16 mma, fp32 softmax/accum).
// CTA = 128 q-rows of one (b,h); 4 warps; thread t owns softmax of q-row t.
// K-tiles of 64. Q pre-scaled by 1/8 at QKV epilogue.
// ---------------------------------------------------------------------------
#define ATT_SMEM_BYTES (128*ATT_LDH*2 + 64*ATT_LDH*2 + 64*ATT_LDH*2 + 128*ATT_LDF*4 + 128*ATT_LDH*2)

__global__ __launch_bounds__(128)
void attn_kernel(const __half* __restrict__ qh, const __half* __restrict__ kh,
                 const __half* __restrict__ vh, __half* __restrict__ ctxh)
{
    extern __shared__ char smraw[];
    __half* sQ = (__half*)smraw;                         // 128 x 72
    __half* sK = sQ + 128 * ATT_LDH;                     // 64 x 72
    __half* sV = sK + 64 * ATT_LDH;                      // 64 x 72
    float*  sS = (float*)(sV + 64 * ATT_LDH);            // 128 x 68 fp32
    __half* sP = (__half*)(sS + 128 * ATT_LDF);          // 128 x 72

    const int tid = threadIdx.x;
    const int wid = tid >> 5;
    const int hh  = blockIdx.y;
    const int bb  = blockIdx.z;
    const int bh  = bb * HH + hh;
    const int q0  = blockIdx.x * 128;
    const int len = g_len[bb];

    // load Q tile (128 x 64 halves)
    {
        const uint4* qg = (const uint4*)(qh + ((size_t)bh * SS + q0) * DD);
#pragma unroll
        for (int i = 0; i < 8; ++i) {
            const int idx = tid + (i << 7);
            const int row = idx >> 3, seg = idx & 7;
            *(uint4*)(sQ + row * ATT_LDH + seg * 8) = qg[row * 8 + seg];
        }
    }

    float o[64];
#pragma unroll
    for (int j = 0; j < 64; ++j) o[j] = 0.f;
    float m = -1e30f, l = 0.f;

    const uint4* kg = (const uint4*)(kh + (size_t)bh * SS * DD);
    const uint4* vg = (const uint4*)(vh + (size_t)bh * SS * DD);

    for (int j0 = 0; j0 < len; j0 += 64) {
        __syncthreads();
#pragma unroll
        for (int i = 0; i < 4; ++i) {
            const int idx = tid + (i << 7);
            const int row = idx >> 3, seg = idx & 7;
            *(uint4*)(sK + row * ATT_LDH + seg * 8) = kg[(j0 + row) * 8 + seg];
            *(uint4*)(sV + row * ATT_LDH + seg * 8) = vg[(j0 + row) * 8 + seg];
        }
        __syncthreads();

        // S = Q @ K^T  (warp: 32 rows x 64 cols)
        {
            wmma::fragment<wmma::accumulator, 16, 16, 16, float> sacc[2][4];
#pragma unroll
            for (int i = 0; i < 2; ++i)
#pragma unroll
                for (int j = 0; j < 4; ++j) wmma::fill_fragment(sacc[i][j], 0.0f);
#pragma unroll
            for (int kk = 0; kk < 4; ++kk) {
                wmma::fragment<wmma::matrix_a, 16, 16, 16, __half, wmma::row_major> af[2];
                wmma::fragment<wmma::matrix_b, 16, 16, 16, __half, wmma::col_major> bf[4];
#pragma unroll
                for (int i = 0; i < 2; ++i)
                    wmma::load_matrix_sync(af[i], sQ + (wid * 32 + i * 16) * ATT_LDH + kk * 16, ATT_LDH);
#pragma unroll
                for (int j = 0; j < 4; ++j)
                    wmma::load_matrix_sync(bf[j], sK + (j * 16) * ATT_LDH + kk * 16, ATT_LDH);
#pragma unroll
                for (int i = 0; i < 2; ++i)
#pragma unroll
                    for (int j = 0; j < 4; ++j)
                        wmma::mma_sync(sacc[i][j], af[i], bf[j], sacc[i][j]);
            }
#pragma unroll
            for (int i = 0; i < 2; ++i)
#pragma unroll
                for (int j = 0; j < 4; ++j)
                    wmma::store_matrix_sync(sS + (wid * 32 + i * 16) * ATT_LDF + j * 16,
                                            sacc[i][j], ATT_LDF, wmma::mem_row_major);
        }
        __syncthreads();

        // per-row softmax (thread t <-> q-row t)
        {
            const int nk = min(64, len - j0);
            const float* srow = sS + tid * ATT_LDF;
            float mt = -1e30f;
            for (int j = 0; j < nk; ++j) mt = fmaxf(mt, srow[j]);
            const float mnew = fmaxf(m, mt);
            const float corr = __expf(m - mnew);
            l *= corr;
            __half* prow = sP + tid * ATT_LDH;
            for (int j = 0; j < 64; ++j) {
                float p = 0.f;
                if (j < nk) { p = __expf(srow[j] - mnew); l += p; }
                prow[j] = __float2half_rn(p);
            }
            m = mnew;
#pragma unroll
            for (int j = 0; j < 64; ++j) o[j] *= corr;
        }
        __syncthreads();

        // O_part = P @ V
        {
            wmma::fragment<wmma::accumulator, 16, 16, 16, float> oacc[2][4];
#pragma unroll
            for (int i = 0; i < 2; ++i)
#pragma unroll
                for (int j = 0; j < 4; ++j) wmma::fill_fragment(oacc[i][j], 0.0f);
#pragma unroll
            for (int kk = 0; kk < 4; ++kk) {
                wmma::fragment<wmma::matrix_a, 16, 16, 16, __half, wmma::row_major> af[2];
                wmma::fragment<wmma::matrix_b, 16, 16, 16, __half, wmma::row_major> bf[4];
#pragma unroll
                for (int i = 0; i < 2; ++i)
                    wmma::load_matrix_sync(af[i], sP + (wid * 32 + i * 16) * ATT_LDH + kk * 16, ATT_LDH);
#pragma unroll
                for (int j = 0; j < 4; ++j)
                    wmma::load_matrix_sync(bf[j], sV + (kk * 16) * ATT_LDH + j * 16, ATT_LDH);
#pragma unroll
                for (int i = 0; i < 2; ++i)
#pragma unroll
                    for (int j = 0; j < 4; ++j)
                        wmma::mma_sync(oacc[i][j], af[i], bf[j], oacc[i][j]);
            }
#pragma unroll
            for (int i = 0; i < 2; ++i)
#pragma unroll
                for (int j = 0; j < 4; ++j)
                    wmma::store_matrix_sync(sS + (wid * 32 + i * 16) * ATT_LDF + j * 16,
                                            oacc[i][j], ATT_LDF, wmma::mem_row_major);
        }
        __syncthreads();

        {
            const float* orow = sS + tid * ATT_LDF;
#pragma unroll
            for (int j = 0; j < 64; ++j) o[j] += orow[j];
        }
    }

    const float fin = (q0 + tid < len) ? (1.0f / l) : 0.f;
    __half2* og = (__half2*)(ctxh + ((size_t)bb * SS + q0 + tid) * EE + hh * DD);
#pragma unroll
    for (int j = 0; j < 32; ++j)
        og[j] = __floats2half2_rn(o[2 * j] * fin, o[2 * j + 1] * fin);
}

// ---------------------------------------------------------------------------
// Launch
// ---------------------------------------------------------------------------
extern "C" void kernel_launch(void* const* d_in, const int* in_sizes, int n_in,
                              void* d_out, int out_size)
{
    const float* x            = (const float*)d_in[0];
    const unsigned char* mask = (const unsigned char*)d_in[1];
    const float* Wqkv_w       = (const float*)d_in[2];
    const float* Wqkv_b       = (const float*)d_in[3];
    const float* out_w        = (const float*)d_in[4];
    const float* out_b        = (const float*)d_in[5];
    float* out                = (float*)d_out;

    __half *xh, *wqkvh, *owh, *qh, *kh, *vh, *ctxh;
    cudaGetSymbolAddress((void**)&xh,    g_xh);
    cudaGetSymbolAddress((void**)&wqkvh, g_wqkvh);
    cudaGetSymbolAddress((void**)&owh,   g_owh);
    cudaGetSymbolAddress((void**)&qh,    g_qh);
    cudaGetSymbolAddress((void**)&kh,    g_kh);
    cudaGetSymbolAddress((void**)&vh,    g_vh);
    cudaGetSymbolAddress((void**)&ctxh,  g_ctxh);

    // 1) lengths + fp16 conversions
    lengths_kernel<<<BB, 32>>>(mask);
    conv_kernel<<<(BB * SS * EE / 4 + 255) / 256, 256>>>(x, xh, BB * SS * EE / 4);
    conv_kernel<<<(3 * EE * EE / 4 + 255) / 256, 256>>>(Wqkv_w, wqkvh, 3 * EE * EE / 4);
    conv_kernel<<<(EE * EE / 4 + 255) / 256, 256>>>(out_w, owh, EE * EE / 4);

    // 2) QKV projection (fp16 wmma + cp.async): -> q/k/v fp16, q pre-scaled
    cudaFuncSetAttribute(tc_gemm<0>, cudaFuncAttributeMaxDynamicSharedMemorySize, GEMM_SMEM_BYTES);
    cudaFuncSetAttribute(tc_gemm<1>, cudaFuncAttributeMaxDynamicSharedMemorySize, GEMM_SMEM_BYTES);
    {
        dim3 grid(3 * EE / BN, (BB * SS) / BM);   // (18, 64)
        tc_gemm<0><<<grid, 256, GEMM_SMEM_BYTES>>>(xh, wqkvh, Wqkv_b, nullptr, qh, kh, vh);
    }

    // 3) tensor-core flash attention -> ctx fp16 [B,S,E]
    cudaFuncSetAttribute(attn_kernel, cudaFuncAttributeMaxDynamicSharedMemorySize, ATT_SMEM_BYTES);
    attn_kernel<<<dim3(SS / 128, HH, BB), 128, ATT_SMEM_BYTES>>>(qh, kh, vh, ctxh);

    // 4) output projection (fp16 wmma) -> fp32 out
    {
        dim3 grid(EE / BN, (BB * SS) / BM);       // (6, 64)
        tc_gemm<1><<<grid, 256, GEMM_SMEM_BYTES>>>(ctxh, owh, out_b, out, nullptr, nullptr, nullptr);
    }
}

// round 6
// speedup vs baseline: 5.2905x; 1.2060x over previous
#include <cuda_runtime.h>
#include <cuda_fp16.h>
#include <math.h>
#include <stdint.h>
#include <mma.h>

using namespace nvcuda;

// Problem constants
#define BB 8
#define SS 1024
#define EE 768
#define HH 12
#define DD 64

// GEMM tiling
#define BM 128
#define BN 128
#define BK 64
#define LDH 72            // padded halves stride in smem tiles
#define LDS_C 132         // padded fp32 stride for epilogue tile

// Attention smem strides
#define ATT_LDH 72        // halves
#define ATT_LDF 68        // fp32

// Scratch (allocation-free rule: __device__ globals)
__device__ __half g_xh[(size_t)BB * SS * EE];
__device__ __half g_wqkvh[(size_t)3 * EE * EE];
__device__ __half g_owh[(size_t)EE * EE];
__device__ __half g_qh[(size_t)BB * HH * SS * DD];
__device__ __half g_kh[(size_t)BB * HH * SS * DD];
__device__ __half g_vh[(size_t)BB * HH * SS * DD];
__device__ __half g_ctxh[(size_t)BB * SS * EE];
__device__ int    g_len[BB];

// ---------------------------------------------------------------------------
// fp32 -> fp16 conversion (RN)
// ---------------------------------------------------------------------------
__global__ void conv_kernel(const float* __restrict__ src, __half* __restrict__ dst, int n4)
{
    const int i = blockIdx.x * 256 + threadIdx.x;
    if (i < n4) {
        const float4 v = ((const float4*)src)[i];
        ((__half2*)dst)[i * 2]     = __floats2half2_rn(v.x, v.y);
        ((__half2*)dst)[i * 2 + 1] = __floats2half2_rn(v.z, v.w);
    }
}

// ---------------------------------------------------------------------------
// Mask -> per-batch valid length (prefix mask; count nonzeros).
// ---------------------------------------------------------------------------
__global__ void lengths_kernel(const unsigned char* __restrict__ mask)
{
    const int b = blockIdx.x;
    const int lane = threadIdx.x;
    int cnt = 0;
    if (mask[1] != 0) {
        const unsigned char* row = mask + (size_t)b * SS;
        for (int i = lane; i < SS; i += 32) cnt += (row[i] != 0);
    } else {
        const unsigned int* row = (const unsigned int*)mask + (size_t)b * SS;
        for (int i = lane; i < SS; i += 32) cnt += (row[i] != 0u);
    }
#pragma unroll
    for (int o = 16; o; o >>= 1) cnt += __shfl_xor_sync(0xffffffffu, cnt, o);
    if (lane == 0) g_len[b] = cnt;
}

// ---------------------------------------------------------------------------
// fp16 wmma GEMM (unchanged from R5 — known good).
// ---------------------------------------------------------------------------
#define GEMM_SMEM_BYTES (2 * 2 * BM * LDH * 2)

template <int MODE>
__global__ __launch_bounds__(256, 2)
void tc_gemm(const __half* __restrict__ A, const __half* __restrict__ W,
             const float* __restrict__ bias, float* __restrict__ C,
             __half* __restrict__ Qo, __half* __restrict__ Ko, __half* __restrict__ Vo)
{
    extern __shared__ char smraw[];
    __half* sbuf = (__half*)smraw;
    float*  Cs   = (float*)smraw;

    const int tid    = threadIdx.x;
    const int wid    = tid >> 5;
    const int warp_m = wid & 3;
    const int warp_n = wid >> 2;
    const int m0     = blockIdx.y * BM;
    const int n0     = blockIdx.x * BN;

    const __half* Abase = A + (size_t)m0 * EE;
    const __half* Wbase = W + (size_t)n0 * EE;

    wmma::fragment<wmma::accumulator, 16, 16, 16, float> acc[2][4];
#pragma unroll
    for (int i = 0; i < 2; ++i)
#pragma unroll
        for (int j = 0; j < 4; ++j) wmma::fill_fragment(acc[i][j], 0.0f);

    auto issue_tile = [&](int t, int buf) {
        const __half* Ag = Abase + t * BK;
        const __half* Wg = Wbase + t * BK;
        __half* sA = sbuf + buf * (2 * BM * LDH);
        __half* sB = sA + BM * LDH;
#pragma unroll
        for (int i = 0; i < 4; ++i) {
            const int idx = tid + (i << 8);
            const int row = idx >> 3;
            const int seg = idx & 7;
            const __half* srcA = Ag + (size_t)row * EE + seg * 8;
            const __half* srcB = Wg + (size_t)row * EE + seg * 8;
            uint32_t dA = (uint32_t)__cvta_generic_to_shared(sA + row * LDH + seg * 8);
            uint32_t dB = (uint32_t)__cvta_generic_to_shared(sB + row * LDH + seg * 8);
            asm volatile("cp.async.cg.shared.global [%0], [%1], 16;" :: "r"(dA), "l"(srcA));
            asm volatile("cp.async.cg.shared.global [%0], [%1], 16;" :: "r"(dB), "l"(srcB));
        }
        asm volatile("cp.async.commit_group;" ::: "memory");
    };

    issue_tile(0, 0);

    const int nT = EE / BK;    // 12
    for (int t = 0; t < nT; ++t) {
        if (t + 1 < nT) {
            issue_tile(t + 1, (t + 1) & 1);
            asm volatile("cp.async.wait_group 1;" ::: "memory");
        } else {
            asm volatile("cp.async.wait_group 0;" ::: "memory");
        }
        __syncthreads();

        const __half* sA = sbuf + (t & 1) * (2 * BM * LDH);
        const __half* sB = sA + BM * LDH;
#pragma unroll
        for (int kk = 0; kk < BK / 16; ++kk) {
            wmma::fragment<wmma::matrix_a, 16, 16, 16, __half, wmma::row_major> af[2];
            wmma::fragment<wmma::matrix_b, 16, 16, 16, __half, wmma::col_major> bf[4];
#pragma unroll
            for (int i = 0; i < 2; ++i)
                wmma::load_matrix_sync(af[i], sA + (warp_m * 32 + i * 16) * LDH + kk * 16, LDH);
#pragma unroll
            for (int j = 0; j < 4; ++j)
                wmma::load_matrix_sync(bf[j], sB + (warp_n * 64 + j * 16) * LDH + kk * 16, LDH);
#pragma unroll
            for (int i = 0; i < 2; ++i)
#pragma unroll
                for (int j = 0; j < 4; ++j)
                    wmma::mma_sync(acc[i][j], af[i], bf[j], acc[i][j]);
        }
        __syncthreads();
    }

#pragma unroll
    for (int i = 0; i < 2; ++i)
#pragma unroll
        for (int j = 0; j < 4; ++j)
            wmma::store_matrix_sync(Cs + (warp_m * 32 + i * 16) * LDS_C + warp_n * 64 + j * 16,
                                    acc[i][j], LDS_C, wmma::mem_row_major);
    __syncthreads();

#pragma unroll
    for (int i = 0; i < 16; ++i) {
        const int fi  = tid + (i << 8);
        const int row = fi >> 5;
        const int col = (fi & 31) * 4;
        const int m = m0 + row;
        const int n = n0 + col;
        float4 o = *(const float4*)(Cs + row * LDS_C + col);
        const float4 bv = *(const float4*)(bias + n);
        o.x += bv.x; o.y += bv.y; o.z += bv.z; o.w += bv.w;
        if (MODE == 0) {
            const int c  = n / EE;
            const int rr = n - c * EE;
            const int h  = rr >> 6;
            const int d  = rr & 63;
            const int b  = m >> 10;
            const int s  = m & 1023;
            if (c == 0) { o.x *= 0.125f; o.y *= 0.125f; o.z *= 0.125f; o.w *= 0.125f; }
            __half* dst = ((c == 0) ? Qo : (c == 1) ? Ko : Vo)
                          + ((((size_t)b * HH + h) * SS + s) * DD + d);
            *(__half2*)(dst)     = __floats2half2_rn(o.x, o.y);
            *(__half2*)(dst + 2) = __floats2half2_rn(o.z, o.w);
        } else {
            *(float4*)(C + (size_t)m * EE + n) = o;
        }
    }
}

// ---------------------------------------------------------------------------
// Tensor-core flash attention v2:
// 256 threads / 8 warps; warp owns 16 q-rows; softmax split 2 threads/row;
// cp.async double-buffered K/V tiles; fp32 softmax & O accumulation.
// smem: sQ 128x72h | sK 2x64x72h | sV 2x64x72h | sS 128x68f | sP 128x72h
// ---------------------------------------------------------------------------
#define ATT_SMEM_BYTES (128*ATT_LDH*2 + 2*64*ATT_LDH*2 + 2*64*ATT_LDH*2 + 128*ATT_LDF*4 + 128*ATT_LDH*2)

__global__ __launch_bounds__(256, 1)
void attn_kernel(const __half* __restrict__ qh, const __half* __restrict__ kh,
                 const __half* __restrict__ vh, __half* __restrict__ ctxh)
{
    extern __shared__ char smraw[];
    __half* sQ  = (__half*)smraw;                        // 128 x 72
    __half* sK0 = sQ + 128 * ATT_LDH;                    // 2 x (64 x 72)
    __half* sV0 = sK0 + 2 * 64 * ATT_LDH;                // 2 x (64 x 72)
    float*  sS  = (float*)(sV0 + 2 * 64 * ATT_LDH);      // 128 x 68 fp32
    __half* sP  = (__half*)(sS + 128 * ATT_LDF);         // 128 x 72

    const int tid  = threadIdx.x;
    const int wid  = tid >> 5;
    const int hh   = blockIdx.y;
    const int bb   = blockIdx.z;
    const int bh   = bb * HH + hh;
    const int q0   = blockIdx.x * 128;
    const int len  = g_len[bb];
    const int row  = tid >> 1;          // softmax row 0..127
    const int half = tid & 1;           // column half (32 cols each)

    // load Q tile (128 x 64 halves), 1024 uint4 / 256 thr
    {
        const uint4* qg = (const uint4*)(qh + ((size_t)bh * SS + q0) * DD);
#pragma unroll
        for (int i = 0; i < 4; ++i) {
            const int idx = tid + (i << 8);
            const int r = idx >> 3, seg = idx & 7;
            *(uint4*)(sQ + r * ATT_LDH + seg * 8) = qg[r * 8 + seg];
        }
    }

    const uint4* kg = (const uint4*)(kh + (size_t)bh * SS * DD);
    const uint4* vg = (const uint4*)(vh + (size_t)bh * SS * DD);

    // cp.async one 64x64 K tile + V tile into buffer `buf`
    auto issue_kv = [&](int j0, int buf) {
        __half* dK = sK0 + buf * (64 * ATT_LDH);
        __half* dV = sV0 + buf * (64 * ATT_LDH);
#pragma unroll
        for (int i = 0; i < 2; ++i) {
            const int idx = tid + (i << 8);          // 0..511
            const int r = idx >> 3, seg = idx & 7;
            const uint4* sk = &kg[(j0 + r) * 8 + seg];
            const uint4* sv = &vg[(j0 + r) * 8 + seg];
            uint32_t aK = (uint32_t)__cvta_generic_to_shared(dK + r * ATT_LDH + seg * 8);
            uint32_t aV = (uint32_t)__cvta_generic_to_shared(dV + r * ATT_LDH + seg * 8);
            asm volatile("cp.async.cg.shared.global [%0], [%1], 16;" :: "r"(aK), "l"(sk));
            asm volatile("cp.async.cg.shared.global [%0], [%1], 16;" :: "r"(aV), "l"(sv));
        }
        asm volatile("cp.async.commit_group;" ::: "memory");
    };

    float o[32];
#pragma unroll
    for (int j = 0; j < 32; ++j) o[j] = 0.f;
    float m = -1e30f, l = 0.f;

    const int nTiles = (len + 63) >> 6;
    issue_kv(0, 0);

    for (int t = 0; t < nTiles; ++t) {
        const int j0  = t << 6;
        const int buf = t & 1;
        if (t + 1 < nTiles) {
            issue_kv(j0 + 64, buf ^ 1);
            asm volatile("cp.async.wait_group 1;" ::: "memory");
        } else {
            asm volatile("cp.async.wait_group 0;" ::: "memory");
        }
        __syncthreads();

        const __half* sK = sK0 + buf * (64 * ATT_LDH);
        const __half* sV = sV0 + buf * (64 * ATT_LDH);

        // S = Q @ K^T : warp computes 16 rows x 64 cols
        {
            wmma::fragment<wmma::accumulator, 16, 16, 16, float> sacc[4];
#pragma unroll
            for (int j = 0; j < 4; ++j) wmma::fill_fragment(sacc[j], 0.0f);
#pragma unroll
            for (int kk = 0; kk < 4; ++kk) {
                wmma::fragment<wmma::matrix_a, 16, 16, 16, __half, wmma::row_major> af;
                wmma::load_matrix_sync(af, sQ + (wid * 16) * ATT_LDH + kk * 16, ATT_LDH);
#pragma unroll
                for (int j = 0; j < 4; ++j) {
                    wmma::fragment<wmma::matrix_b, 16, 16, 16, __half, wmma::col_major> bf;
                    wmma::load_matrix_sync(bf, sK + (j * 16) * ATT_LDH + kk * 16, ATT_LDH);
                    wmma::mma_sync(sacc[j], af, bf, sacc[j]);
                }
            }
#pragma unroll
            for (int j = 0; j < 4; ++j)
                wmma::store_matrix_sync(sS + (wid * 16) * ATT_LDF + j * 16,
                                        sacc[j], ATT_LDF, wmma::mem_row_major);
        }
        __syncthreads();

        // softmax: 2 threads per row, 32 cols each
        {
            const int nk = min(64, len - j0);
            const float* srow = sS + row * ATT_LDF + half * 32;
            float4 sc[8];
#pragma unroll
            for (int i = 0; i < 8; ++i) sc[i] = *(const float4*)(srow + i * 4);

            float mt = -1e30f;
            const int base = half * 32;
#pragma unroll
            for (int i = 0; i < 8; ++i) {
                if (base + i * 4 + 0 < nk) mt = fmaxf(mt, sc[i].x);
                if (base + i * 4 + 1 < nk) mt = fmaxf(mt, sc[i].y);
                if (base + i * 4 + 2 < nk) mt = fmaxf(mt, sc[i].z);
                if (base + i * 4 + 3 < nk) mt = fmaxf(mt, sc[i].w);
            }
            mt = fmaxf(mt, __shfl_xor_sync(0xffffffffu, mt, 1));
            const float mnew = fmaxf(m, mt);
            const float corr = __expf(m - mnew);

            float ls = 0.f;
            __half2* prow = (__half2*)(sP + row * ATT_LDH + half * 32);
#pragma unroll
            for (int i = 0; i < 8; ++i) {
                float p0 = (base + i * 4 + 0 < nk) ? __expf(sc[i].x - mnew) : 0.f;
                float p1 = (base + i * 4 + 1 < nk) ? __expf(sc[i].y - mnew) : 0.f;
                float p2 = (base + i * 4 + 2 < nk) ? __expf(sc[i].z - mnew) : 0.f;
                float p3 = (base + i * 4 + 3 < nk) ? __expf(sc[i].w - mnew) : 0.f;
                ls += (p0 + p1) + (p2 + p3);
                prow[i * 2]     = __floats2half2_rn(p0, p1);
                prow[i * 2 + 1] = __floats2half2_rn(p2, p3);
            }
            l = l * corr + ls + __shfl_xor_sync(0xffffffffu, ls, 1);
            m = mnew;
#pragma unroll
            for (int j = 0; j < 32; ++j) o[j] *= corr;
        }
        __syncthreads();

        // O_part = P @ V : warp computes 16 rows x 64 cols
        {
            wmma::fragment<wmma::accumulator, 16, 16, 16, float> oacc[4];
#pragma unroll
            for (int j = 0; j < 4; ++j) wmma::fill_fragment(oacc[j], 0.0f);
#pragma unroll
            for (int kk = 0; kk < 4; ++kk) {
                wmma::fragment<wmma::matrix_a, 16, 16, 16, __half, wmma::row_major> af;
                wmma::load_matrix_sync(af, sP + (wid * 16) * ATT_LDH + kk * 16, ATT_LDH);
#pragma unroll
                for (int j = 0; j < 4; ++j) {
                    wmma::fragment<wmma::matrix_b, 16, 16, 16, __half, wmma::row_major> bf;
                    wmma::load_matrix_sync(bf, sV + (kk * 16) * ATT_LDH + j * 16, ATT_LDH);
                    wmma::mma_sync(oacc[j], af, bf, oacc[j]);
                }
            }
#pragma unroll
            for (int j = 0; j < 4; ++j)
                wmma::store_matrix_sync(sS + (wid * 16) * ATT_LDF + j * 16,
                                        oacc[j], ATT_LDF, wmma::mem_row_major);
        }
        __syncthreads();

        {
            const float* orow = sS + row * ATT_LDF + half * 32;
#pragma unroll
            for (int i = 0; i < 8; ++i) {
                const float4 ov = *(const float4*)(orow + i * 4);
                o[i * 4 + 0] += ov.x; o[i * 4 + 1] += ov.y;
                o[i * 4 + 2] += ov.z; o[i * 4 + 3] += ov.w;
            }
        }
        __syncthreads();
    }

    const float fin = (q0 + row < len) ? (1.0f / l) : 0.f;
    __half2* og = (__half2*)(ctxh + ((size_t)bb * SS + q0 + row) * EE + hh * DD + half * 32);
#pragma unroll
    for (int j = 0; j < 16; ++j)
        og[j] = __floats2half2_rn(o[2 * j] * fin, o[2 * j + 1] * fin);
}

// ---------------------------------------------------------------------------
// Launch
// ---------------------------------------------------------------------------
extern "C" void kernel_launch(void* const* d_in, const int* in_sizes, int n_in,
                              void* d_out, int out_size)
{
    const float* x            = (const float*)d_in[0];
    const unsigned char* mask = (const unsigned char*)d_in[1];
    const float* Wqkv_w       = (const float*)d_in[2];
    const float* Wqkv_b       = (const float*)d_in[3];
    const float* out_w        = (const float*)d_in[4];
    const float* out_b        = (const float*)d_in[5];
    float* out                = (float*)d_out;

    __half *xh, *wqkvh, *owh, *qh, *kh, *vh, *ctxh;
    cudaGetSymbolAddress((void**)&xh,    g_xh);
    cudaGetSymbolAddress((void**)&wqkvh, g_wqkvh);
    cudaGetSymbolAddress((void**)&owh,   g_owh);
    cudaGetSymbolAddress((void**)&qh,    g_qh);
    cudaGetSymbolAddress((void**)&kh,    g_kh);
    cudaGetSymbolAddress((void**)&vh,    g_vh);
    cudaGetSymbolAddress((void**)&ctxh,  g_ctxh);

    // 1) lengths + fp16 conversions
    lengths_kernel<<<BB, 32>>>(mask);
    conv_kernel<<<(BB * SS * EE / 4 + 255) / 256, 256>>>(x, xh, BB * SS * EE / 4);
    conv_kernel<<<(3 * EE * EE / 4 + 255) / 256, 256>>>(Wqkv_w, wqkvh, 3 * EE * EE / 4);
    conv_kernel<<<(EE * EE / 4 + 255) / 256, 256>>>(out_w, owh, EE * EE / 4);

    // 2) QKV projection (fp16 wmma + cp.async) -> q/k/v fp16 (q pre-scaled)
    cudaFuncSetAttribute(tc_gemm<0>, cudaFuncAttributeMaxDynamicSharedMemorySize, GEMM_SMEM_BYTES);
    cudaFuncSetAttribute(tc_gemm<1>, cudaFuncAttributeMaxDynamicSharedMemorySize, GEMM_SMEM_BYTES);
    {
        dim3 grid(3 * EE / BN, (BB * SS) / BM);
        tc_gemm<0><<<grid, 256, GEMM_SMEM_BYTES>>>(xh, wqkvh, Wqkv_b, nullptr, qh, kh, vh);
    }

    // 3) tensor-core flash attention -> ctx fp16 [B,S,E]
    cudaFuncSetAttribute(attn_kernel, cudaFuncAttributeMaxDynamicSharedMemorySize, ATT_SMEM_BYTES);
    attn_kernel<<<dim3(SS / 128, HH, BB), 256, ATT_SMEM_BYTES>>>(qh, kh, vh, ctxh);

    // 4) output projection (fp16 wmma) -> fp32 out
    {
        dim3 grid(EE / BN, (BB * SS) / BM);
        tc_gemm<1><<<grid, 256, GEMM_SMEM_BYTES>>>(ctxh, owh, out_b, out, nullptr, nullptr, nullptr);
    }
}

// round 7
// speedup vs baseline: 7.9652x; 1.5056x over previous
#include <cuda_runtime.h>
#include <cuda_fp16.h>
#include <math.h>
#include <stdint.h>
#include <mma.h>

using namespace nvcuda;

// Problem constants
#define BB 8
#define SS 1024
#define EE 768
#define HH 12
#define DD 64

// GEMM tiling
#define BM 128
#define BN 128
#define BK 64
#define LDH 72            // padded halves stride in smem tiles
#define LDS_C 132         // padded fp32 stride for epilogue tile

// Attention smem stride (halves)
#define ATT_LDH 72

// Scratch (allocation-free rule: __device__ globals)
__device__ __half g_xh[(size_t)BB * SS * EE];
__device__ __half g_wqkvh[(size_t)3 * EE * EE];
__device__ __half g_owh[(size_t)EE * EE];
__device__ __half g_qh[(size_t)BB * HH * SS * DD];
__device__ __half g_kh[(size_t)BB * HH * SS * DD];
__device__ __half g_vh[(size_t)BB * HH * SS * DD];
__device__ __half g_ctxh[(size_t)BB * SS * EE];
__device__ int    g_len[BB];

__device__ __forceinline__ uint32_t packh2(float a, float b) {
    __half2 h = __floats2half2_rn(a, b);
    return *(uint32_t*)&h;
}

// ---------------------------------------------------------------------------
// fp32 -> fp16 conversion (RN)
// ---------------------------------------------------------------------------
__global__ void conv_kernel(const float* __restrict__ src, __half* __restrict__ dst, int n4)
{
    const int i = blockIdx.x * 256 + threadIdx.x;
    if (i < n4) {
        const float4 v = ((const float4*)src)[i];
        ((__half2*)dst)[i * 2]     = __floats2half2_rn(v.x, v.y);
        ((__half2*)dst)[i * 2 + 1] = __floats2half2_rn(v.z, v.w);
    }
}

// ---------------------------------------------------------------------------
// Mask -> per-batch valid length (prefix mask; count nonzeros).
// ---------------------------------------------------------------------------
__global__ void lengths_kernel(const unsigned char* __restrict__ mask)
{
    const int b = blockIdx.x;
    const int lane = threadIdx.x;
    int cnt = 0;
    if (mask[1] != 0) {
        const unsigned char* row = mask + (size_t)b * SS;
        for (int i = lane; i < SS; i += 32) cnt += (row[i] != 0);
    } else {
        const unsigned int* row = (const unsigned int*)mask + (size_t)b * SS;
        for (int i = lane; i < SS; i += 32) cnt += (row[i] != 0u);
    }
#pragma unroll
    for (int o = 16; o; o >>= 1) cnt += __shfl_xor_sync(0xffffffffu, cnt, o);
    if (lane == 0) g_len[b] = cnt;
}

// ---------------------------------------------------------------------------
// fp16 wmma GEMM (unchanged — known good).
// ---------------------------------------------------------------------------
#define GEMM_SMEM_BYTES (2 * 2 * BM * LDH * 2)

template <int MODE>
__global__ __launch_bounds__(256, 2)
void tc_gemm(const __half* __restrict__ A, const __half* __restrict__ W,
             const float* __restrict__ bias, float* __restrict__ C,
             __half* __restrict__ Qo, __half* __restrict__ Ko, __half* __restrict__ Vo)
{
    extern __shared__ char smraw[];
    __half* sbuf = (__half*)smraw;
    float*  Cs   = (float*)smraw;

    const int tid    = threadIdx.x;
    const int wid    = tid >> 5;
    const int warp_m = wid & 3;
    const int warp_n = wid >> 2;
    const int m0     = blockIdx.y * BM;
    const int n0     = blockIdx.x * BN;

    const __half* Abase = A + (size_t)m0 * EE;
    const __half* Wbase = W + (size_t)n0 * EE;

    wmma::fragment<wmma::accumulator, 16, 16, 16, float> acc[2][4];
#pragma unroll
    for (int i = 0; i < 2; ++i)
#pragma unroll
        for (int j = 0; j < 4; ++j) wmma::fill_fragment(acc[i][j], 0.0f);

    auto issue_tile = [&](int t, int buf) {
        const __half* Ag = Abase + t * BK;
        const __half* Wg = Wbase + t * BK;
        __half* sA = sbuf + buf * (2 * BM * LDH);
        __half* sB = sA + BM * LDH;
#pragma unroll
        for (int i = 0; i < 4; ++i) {
            const int idx = tid + (i << 8);
            const int row = idx >> 3;
            const int seg = idx & 7;
            const __half* srcA = Ag + (size_t)row * EE + seg * 8;
            const __half* srcB = Wg + (size_t)row * EE + seg * 8;
            uint32_t dA = (uint32_t)__cvta_generic_to_shared(sA + row * LDH + seg * 8);
            uint32_t dB = (uint32_t)__cvta_generic_to_shared(sB + row * LDH + seg * 8);
            asm volatile("cp.async.cg.shared.global [%0], [%1], 16;" :: "r"(dA), "l"(srcA));
            asm volatile("cp.async.cg.shared.global [%0], [%1], 16;" :: "r"(dB), "l"(srcB));
        }
        asm volatile("cp.async.commit_group;" ::: "memory");
    };

    issue_tile(0, 0);

    const int nT = EE / BK;    // 12
    for (int t = 0; t < nT; ++t) {
        if (t + 1 < nT) {
            issue_tile(t + 1, (t + 1) & 1);
            asm volatile("cp.async.wait_group 1;" ::: "memory");
        } else {
            asm volatile("cp.async.wait_group 0;" ::: "memory");
        }
        __syncthreads();

        const __half* sA = sbuf + (t & 1) * (2 * BM * LDH);
        const __half* sB = sA + BM * LDH;
#pragma unroll
        for (int kk = 0; kk < BK / 16; ++kk) {
            wmma::fragment<wmma::matrix_a, 16, 16, 16, __half, wmma::row_major> af[2];
            wmma::fragment<wmma::matrix_b, 16, 16, 16, __half, wmma::col_major> bf[4];
#pragma unroll
            for (int i = 0; i < 2; ++i)
                wmma::load_matrix_sync(af[i], sA + (warp_m * 32 + i * 16) * LDH + kk * 16, LDH);
#pragma unroll
            for (int j = 0; j < 4; ++j)
                wmma::load_matrix_sync(bf[j], sB + (warp_n * 64 + j * 16) * LDH + kk * 16, LDH);
#pragma unroll
            for (int i = 0; i < 2; ++i)
#pragma unroll
                for (int j = 0; j < 4; ++j)
                    wmma::mma_sync(acc[i][j], af[i], bf[j], acc[i][j]);
        }
        __syncthreads();
    }

#pragma unroll
    for (int i = 0; i < 2; ++i)
#pragma unroll
        for (int j = 0; j < 4; ++j)
            wmma::store_matrix_sync(Cs + (warp_m * 32 + i * 16) * LDS_C + warp_n * 64 + j * 16,
                                    acc[i][j], LDS_C, wmma::mem_row_major);
    __syncthreads();

#pragma unroll
    for (int i = 0; i < 16; ++i) {
        const int fi  = tid + (i << 8);
        const int row = fi >> 5;
        const int col = (fi & 31) * 4;
        const int m = m0 + row;
        const int n = n0 + col;
        float4 o = *(const float4*)(Cs + row * LDS_C + col);
        const float4 bv = *(const float4*)(bias + n);
        o.x += bv.x; o.y += bv.y; o.z += bv.z; o.w += bv.w;
        if (MODE == 0) {
            const int c  = n / EE;
            const int rr = n - c * EE;
            const int h  = rr >> 6;
            const int d  = rr & 63;
            const int b  = m >> 10;
            const int s  = m & 1023;
            if (c == 0) { o.x *= 0.125f; o.y *= 0.125f; o.z *= 0.125f; o.w *= 0.125f; }
            __half* dst = ((c == 0) ? Qo : (c == 1) ? Ko : Vo)
                          + ((((size_t)b * HH + h) * SS + s) * DD + d);
            *(__half2*)(dst)     = __floats2half2_rn(o.x, o.y);
            *(__half2*)(dst + 2) = __floats2half2_rn(o.z, o.w);
        } else {
            *(float4*)(C + (size_t)m * EE + n) = o;
        }
    }
}

// ---------------------------------------------------------------------------
// Flash attention v3: register-resident FA2 with raw mma.sync.m16n8k16.
// 256 threads / 8 warps; warp owns 16 q-rows. S, softmax, P, O all stay in
// registers. cp.async double-buffered K/V. Early-exit for q0 >= len.
// smem: sQ 128x72h | sK 2x(64x72)h | sV 2x(64x72)h  = 54 KB
// ---------------------------------------------------------------------------
#define ATT_SMEM_BYTES ((128 * ATT_LDH + 4 * 64 * ATT_LDH) * 2)

#define MMA16816(C, A, B)                                                      \
    asm volatile("mma.sync.aligned.m16n8k16.row.col.f32.f16.f16.f32 "          \
        "{%0,%1,%2,%3}, {%4,%5,%6,%7}, {%8,%9}, {%0,%1,%2,%3};"                \
        : "+f"((C)[0]), "+f"((C)[1]), "+f"((C)[2]), "+f"((C)[3])               \
        : "r"((A)[0]), "r"((A)[1]), "r"((A)[2]), "r"((A)[3]),                  \
          "r"((B)[0]), "r"((B)[1]))

#define LDMATRIX_X4(R, ADDR)                                                   \
    asm volatile("ldmatrix.sync.aligned.m8n8.x4.shared.b16 {%0,%1,%2,%3}, [%4];" \
        : "=r"((R)[0]), "=r"((R)[1]), "=r"((R)[2]), "=r"((R)[3]) : "r"(ADDR))

#define LDMATRIX_X4_T(R, ADDR)                                                 \
    asm volatile("ldmatrix.sync.aligned.m8n8.x4.trans.shared.b16 {%0,%1,%2,%3}, [%4];" \
        : "=r"((R)[0]), "=r"((R)[1]), "=r"((R)[2]), "=r"((R)[3]) : "r"(ADDR))

__global__ __launch_bounds__(256, 1)
void attn_kernel(const __half* __restrict__ qh, const __half* __restrict__ kh,
                 const __half* __restrict__ vh, __half* __restrict__ ctxh)
{
    extern __shared__ char smraw[];
    __half* sQ  = (__half*)smraw;                        // 128 x 72
    __half* sK0 = sQ + 128 * ATT_LDH;                    // 2 x (64 x 72)
    __half* sV0 = sK0 + 2 * 64 * ATT_LDH;                // 2 x (64 x 72)

    const int tid  = threadIdx.x;
    const int wid  = tid >> 5;
    const int lane = tid & 31;
    const int gid  = lane >> 2;       // row group within 16-row tile
    const int t4   = lane & 3;        // quad lane (2 cols each)
    const int hh   = blockIdx.y;
    const int bb   = blockIdx.z;
    const int bh   = bb * HH + hh;
    const int q0   = blockIdx.x * 128;
    const int len  = g_len[bb];

    // fully-padded q-block: ctx rows are zero, skip all attention work
    if (q0 >= len) {
#pragma unroll
        for (int i = 0; i < 4; ++i) {
            const int idx = tid + (i << 8);
            const int r = idx >> 3, seg = idx & 7;
            *(uint4*)(ctxh + ((size_t)bb * SS + q0 + r) * EE + hh * DD + seg * 8)
                = make_uint4(0u, 0u, 0u, 0u);
        }
        return;
    }

    // stage Q tile then lift to A-fragments (held for whole kernel)
    {
        const uint4* qg = (const uint4*)(qh + ((size_t)bh * SS + q0) * DD);
#pragma unroll
        for (int i = 0; i < 4; ++i) {
            const int idx = tid + (i << 8);
            const int r = idx >> 3, seg = idx & 7;
            *(uint4*)(sQ + r * ATT_LDH + seg * 8) = qg[r * 8 + seg];
        }
    }
    __syncthreads();

    uint32_t qa[4][4];
    {
        const int r  = wid * 16 + (lane & 15);
        const int c8 = (lane >> 4) * 8;
#pragma unroll
        for (int kk = 0; kk < 4; ++kk) {
            uint32_t a = (uint32_t)__cvta_generic_to_shared(sQ + r * ATT_LDH + kk * 16 + c8);
            LDMATRIX_X4(qa[kk], a);
        }
    }

    const uint4* kg = (const uint4*)(kh + (size_t)bh * SS * DD);
    const uint4* vg = (const uint4*)(vh + (size_t)bh * SS * DD);

    auto issue_kv = [&](int j0, int buf) {
        __half* dK = sK0 + buf * (64 * ATT_LDH);
        __half* dV = sV0 + buf * (64 * ATT_LDH);
#pragma unroll
        for (int i = 0; i < 2; ++i) {
            const int idx = tid + (i << 8);
            const int r = idx >> 3, seg = idx & 7;
            const uint4* sk = &kg[(j0 + r) * 8 + seg];
            const uint4* sv = &vg[(j0 + r) * 8 + seg];
            uint32_t aK = (uint32_t)__cvta_generic_to_shared(dK + r * ATT_LDH + seg * 8);
            uint32_t aV = (uint32_t)__cvta_generic_to_shared(dV + r * ATT_LDH + seg * 8);
            asm volatile("cp.async.cg.shared.global [%0], [%1], 16;" :: "r"(aK), "l"(sk));
            asm volatile("cp.async.cg.shared.global [%0], [%1], 16;" :: "r"(aV), "l"(sv));
        }
        asm volatile("cp.async.commit_group;" ::: "memory");
    };

    float oacc[8][4];
#pragma unroll
    for (int i = 0; i < 8; ++i)
#pragma unroll
        for (int j = 0; j < 4; ++j) oacc[i][j] = 0.f;
    float m0r = -1e30f, m1r = -1e30f, l0 = 0.f, l1 = 0.f;

    const int nTiles = (len + 63) >> 6;
    issue_kv(0, 0);

    for (int t = 0; t < nTiles; ++t) {
        const int j0  = t << 6;
        const int buf = t & 1;
        if (t + 1 < nTiles) {
            issue_kv(j0 + 64, buf ^ 1);
            asm volatile("cp.async.wait_group 1;" ::: "memory");
        } else {
            asm volatile("cp.async.wait_group 0;" ::: "memory");
        }
        __syncthreads();

        const __half* sK = sK0 + buf * (64 * ATT_LDH);
        const __half* sV = sV0 + buf * (64 * ATT_LDH);

        // ---- S = Q @ K^T : 8 n-chunks of 8 cols, fp32 accum in registers
        float sacc[8][4];
#pragma unroll
        for (int i = 0; i < 8; ++i)
#pragma unroll
            for (int j = 0; j < 4; ++j) sacc[i][j] = 0.f;

        {
            const int rb = ((lane >> 4) & 1) * 8 + (lane & 7);
            const int cb = ((lane >> 3) & 1) * 8;
#pragma unroll
            for (int kk = 0; kk < 4; ++kk) {
#pragma unroll
                for (int jc = 0; jc < 8; jc += 2) {
                    uint32_t kb[4];
                    uint32_t a = (uint32_t)__cvta_generic_to_shared(
                        sK + (jc * 8 + rb) * ATT_LDH + kk * 16 + cb);
                    LDMATRIX_X4(kb, a);
                    MMA16816(sacc[jc],     qa[kk], kb);
                    MMA16816(sacc[jc + 1], qa[kk], kb + 2);
                }
            }
        }

        // ---- register softmax (rows gid and gid+8 of warp tile)
        const int nk = min(64, len - j0);
        if (nk < 64) {
#pragma unroll
            for (int jc = 0; jc < 8; ++jc) {
                const int c = jc * 8 + t4 * 2;
                if (c     >= nk) { sacc[jc][0] = -1e30f; sacc[jc][2] = -1e30f; }
                if (c + 1 >= nk) { sacc[jc][1] = -1e30f; sacc[jc][3] = -1e30f; }
            }
        }
        float mt0 = -1e30f, mt1 = -1e30f;
#pragma unroll
        for (int jc = 0; jc < 8; ++jc) {
            mt0 = fmaxf(mt0, fmaxf(sacc[jc][0], sacc[jc][1]));
            mt1 = fmaxf(mt1, fmaxf(sacc[jc][2], sacc[jc][3]));
        }
        mt0 = fmaxf(mt0, __shfl_xor_sync(0xffffffffu, mt0, 1));
        mt0 = fmaxf(mt0, __shfl_xor_sync(0xffffffffu, mt0, 2));
        mt1 = fmaxf(mt1, __shfl_xor_sync(0xffffffffu, mt1, 1));
        mt1 = fmaxf(mt1, __shfl_xor_sync(0xffffffffu, mt1, 2));

        const float mn0 = fmaxf(m0r, mt0), mn1 = fmaxf(m1r, mt1);
        const float corr0 = __expf(m0r - mn0), corr1 = __expf(m1r - mn1);
        m0r = mn0; m1r = mn1;

        float ls0 = 0.f, ls1 = 0.f;
#pragma unroll
        for (int jc = 0; jc < 8; ++jc) {
            sacc[jc][0] = __expf(sacc[jc][0] - mn0);
            sacc[jc][1] = __expf(sacc[jc][1] - mn0);
            sacc[jc][2] = __expf(sacc[jc][2] - mn1);
            sacc[jc][3] = __expf(sacc[jc][3] - mn1);
            ls0 += sacc[jc][0] + sacc[jc][1];
            ls1 += sacc[jc][2] + sacc[jc][3];
        }
        ls0 += __shfl_xor_sync(0xffffffffu, ls0, 1);
        ls0 += __shfl_xor_sync(0xffffffffu, ls0, 2);
        ls1 += __shfl_xor_sync(0xffffffffu, ls1, 1);
        ls1 += __shfl_xor_sync(0xffffffffu, ls1, 2);
        l0 = l0 * corr0 + ls0;
        l1 = l1 * corr1 + ls1;

#pragma unroll
        for (int nc = 0; nc < 8; ++nc) {
            oacc[nc][0] *= corr0; oacc[nc][1] *= corr0;
            oacc[nc][2] *= corr1; oacc[nc][3] *= corr1;
        }

        // ---- O += P @ V : P fragments come straight from sacc
        {
            const int rb = ((lane >> 3) & 1) * 8 + (lane & 7);
            const int cb = (lane >> 4) * 8;
#pragma unroll
            for (int kk = 0; kk < 4; ++kk) {
                uint32_t pa[4];
                pa[0] = packh2(sacc[2 * kk][0],     sacc[2 * kk][1]);
                pa[1] = packh2(sacc[2 * kk][2],     sacc[2 * kk][3]);
                pa[2] = packh2(sacc[2 * kk + 1][0], sacc[2 * kk + 1][1]);
                pa[3] = packh2(sacc[2 * kk + 1][2], sacc[2 * kk + 1][3]);
#pragma unroll
                for (int nc = 0; nc < 8; nc += 2) {
                    uint32_t vb[4];
                    uint32_t a = (uint32_t)__cvta_generic_to_shared(
                        sV + (kk * 16 + rb) * ATT_LDH + nc * 8 + cb);
                    LDMATRIX_X4_T(vb, a);
                    MMA16816(oacc[nc],     pa, vb);
                    MMA16816(oacc[nc + 1], pa, vb + 2);
                }
            }
        }
        __syncthreads();   // all warps done with this buffer before it is refilled
    }

    // ---- epilogue: normalize + write ctx (zero for padded rows)
    const int qrow0 = q0 + wid * 16 + gid;
    const float fin0 = (qrow0     < len) ? (1.0f / l0) : 0.f;
    const float fin1 = (qrow0 + 8 < len) ? (1.0f / l1) : 0.f;
    __half* base0 = ctxh + ((size_t)bb * SS + qrow0) * EE + hh * DD;
    __half* base1 = base0 + (size_t)8 * EE;
#pragma unroll
    for (int nc = 0; nc < 8; ++nc) {
        const int d = nc * 8 + t4 * 2;
        *(__half2*)(base0 + d) = __floats2half2_rn(oacc[nc][0] * fin0, oacc[nc][1] * fin0);
        *(__half2*)(base1 + d) = __floats2half2_rn(oacc[nc][2] * fin1, oacc[nc][3] * fin1);
    }
}

// ---------------------------------------------------------------------------
// Launch
// ---------------------------------------------------------------------------
extern "C" void kernel_launch(void* const* d_in, const int* in_sizes, int n_in,
                              void* d_out, int out_size)
{
    const float* x            = (const float*)d_in[0];
    const unsigned char* mask = (const unsigned char*)d_in[1];
    const float* Wqkv_w       = (const float*)d_in[2];
    const float* Wqkv_b       = (const float*)d_in[3];
    const float* out_w        = (const float*)d_in[4];
    const float* out_b        = (const float*)d_in[5];
    float* out                = (float*)d_out;

    __half *xh, *wqkvh, *owh, *qh, *kh, *vh, *ctxh;
    cudaGetSymbolAddress((void**)&xh,    g_xh);
    cudaGetSymbolAddress((void**)&wqkvh, g_wqkvh);
    cudaGetSymbolAddress((void**)&owh,   g_owh);
    cudaGetSymbolAddress((void**)&qh,    g_qh);
    cudaGetSymbolAddress((void**)&kh,    g_kh);
    cudaGetSymbolAddress((void**)&vh,    g_vh);
    cudaGetSymbolAddress((void**)&ctxh,  g_ctxh);

    // 1) lengths + fp16 conversions
    lengths_kernel<<<BB, 32>>>(mask);
    conv_kernel<<<(BB * SS * EE / 4 + 255) / 256, 256>>>(x, xh, BB * SS * EE / 4);
    conv_kernel<<<(3 * EE * EE / 4 + 255) / 256, 256>>>(Wqkv_w, wqkvh, 3 * EE * EE / 4);
    conv_kernel<<<(EE * EE / 4 + 255) / 256, 256>>>(out_w, owh, EE * EE / 4);

    // 2) QKV projection (fp16 wmma + cp.async) -> q/k/v fp16 (q pre-scaled)
    cudaFuncSetAttribute(tc_gemm<0>, cudaFuncAttributeMaxDynamicSharedMemorySize, GEMM_SMEM_BYTES);
    cudaFuncSetAttribute(tc_gemm<1>, cudaFuncAttributeMaxDynamicSharedMemorySize, GEMM_SMEM_BYTES);
    {
        dim3 grid(3 * EE / BN, (BB * SS) / BM);
        tc_gemm<0><<<grid, 256, GEMM_SMEM_BYTES>>>(xh, wqkvh, Wqkv_b, nullptr, qh, kh, vh);
    }

    // 3) register-resident flash attention -> ctx fp16 [B,S,E]
    cudaFuncSetAttribute(attn_kernel, cudaFuncAttributeMaxDynamicSharedMemorySize, ATT_SMEM_BYTES);
    attn_kernel<<<dim3(SS / 128, HH, BB), 256, ATT_SMEM_BYTES>>>(qh, kh, vh, ctxh);

    // 4) output projection (fp16 wmma) -> fp32 out
    {
        dim3 grid(EE / BN, (BB * SS) / BM);
        tc_gemm<1><<<grid, 256, GEMM_SMEM_BYTES>>>(ctxh, owh, out_b, out, nullptr, nullptr, nullptr);
    }
}

// round 8
// speedup vs baseline: 8.6427x; 1.0851x over previous
#include <cuda_runtime.h>
#include <cuda_fp16.h>
#include <math.h>
#include <stdint.h>
#include <mma.h>

using namespace nvcuda;

// Problem constants
#define BB 8
#define SS 1024
#define EE 768
#define HH 12
#define DD 64

// GEMM tiling
#define BM 128
#define BN 128
#define BK 64
#define LDH 72            // padded halves stride in smem tiles
#define LDS_C 132         // padded fp32 stride for epilogue tile

// Attention smem stride (halves)
#define ATT_LDH 72

// Scratch (allocation-free rule: __device__ globals)
__device__ __half g_xh[(size_t)BB * SS * EE];
__device__ __half g_wqkvh[(size_t)3 * EE * EE];
__device__ __half g_owh[(size_t)EE * EE];
__device__ __half g_qh[(size_t)BB * HH * SS * DD];
__device__ __half g_kh[(size_t)BB * HH * SS * DD];
__device__ __half g_vh[(size_t)BB * HH * SS * DD];
__device__ __half g_ctxh[(size_t)BB * SS * EE];
__device__ int    g_len[BB];

__device__ __forceinline__ uint32_t packh2(float a, float b) {
    __half2 h = __floats2half2_rn(a, b);
    return *(uint32_t*)&h;
}

// ---------------------------------------------------------------------------
// fp32 -> fp16 conversion (RN)
// ---------------------------------------------------------------------------
__global__ void conv_kernel(const float* __restrict__ src, __half* __restrict__ dst, int n4)
{
    const int i = blockIdx.x * 256 + threadIdx.x;
    if (i < n4) {
        const float4 v = ((const float4*)src)[i];
        ((__half2*)dst)[i * 2]     = __floats2half2_rn(v.x, v.y);
        ((__half2*)dst)[i * 2 + 1] = __floats2half2_rn(v.z, v.w);
    }
}

// ---------------------------------------------------------------------------
// Mask -> per-batch valid length (prefix mask; count nonzeros).
// ---------------------------------------------------------------------------
__global__ void lengths_kernel(const unsigned char* __restrict__ mask)
{
    const int b = blockIdx.x;
    const int lane = threadIdx.x;
    int cnt = 0;
    if (mask[1] != 0) {
        const unsigned char* row = mask + (size_t)b * SS;
        for (int i = lane; i < SS; i += 32) cnt += (row[i] != 0);
    } else {
        const unsigned int* row = (const unsigned int*)mask + (size_t)b * SS;
        for (int i = lane; i < SS; i += 32) cnt += (row[i] != 0u);
    }
#pragma unroll
    for (int o = 16; o; o >>= 1) cnt += __shfl_xor_sync(0xffffffffu, cnt, o);
    if (lane == 0) g_len[b] = cnt;
}

// ---------------------------------------------------------------------------
// fp16 wmma GEMM with padded-row skipping.
// MODE 0 (QKV): CTA whose 128-row slab is fully padded -> return (its q/k/v
//   outputs are never consumed: attention reads K/V only below the last
//   computed slab, and padded q-blocks early-exit).
// MODE 1 (out-proj): fully-padded slab -> out rows are exactly bias (ctx=0
//   there); broadcast-fill and return.
// ---------------------------------------------------------------------------
#define GEMM_SMEM_BYTES (2 * 2 * BM * LDH * 2)

template <int MODE>
__global__ __launch_bounds__(256, 2)
void tc_gemm(const __half* __restrict__ A, const __half* __restrict__ W,
             const float* __restrict__ bias, float* __restrict__ C,
             __half* __restrict__ Qo, __half* __restrict__ Ko, __half* __restrict__ Vo)
{
    extern __shared__ char smraw[];
    __half* sbuf = (__half*)smraw;
    float*  Cs   = (float*)smraw;

    const int tid    = threadIdx.x;
    const int wid    = tid >> 5;
    const int warp_m = wid & 3;
    const int warp_n = wid >> 2;
    const int m0     = blockIdx.y * BM;
    const int n0     = blockIdx.x * BN;

    // ---- padded-slab fast paths (128 | 1024, so a slab is in one batch)
    const int len = g_len[m0 >> 10];
    if ((m0 & 1023) >= len) {
        if (MODE == 0) return;   // outputs never consumed
        // MODE 1: out rows = bias (ctx rows are zero)
        for (int idx = tid; idx < BM * (EE / 4); idx += 256) {
            const int row = idx / (EE / 4);
            const int c4  = idx % (EE / 4);
            *(float4*)(C + (size_t)(m0 + row) * EE + c4 * 4) =
                *(const float4*)(bias + c4 * 4);
        }
        return;
    }

    const __half* Abase = A + (size_t)m0 * EE;
    const __half* Wbase = W + (size_t)n0 * EE;

    wmma::fragment<wmma::accumulator, 16, 16, 16, float> acc[2][4];
#pragma unroll
    for (int i = 0; i < 2; ++i)
#pragma unroll
        for (int j = 0; j < 4; ++j) wmma::fill_fragment(acc[i][j], 0.0f);

    auto issue_tile = [&](int t, int buf) {
        const __half* Ag = Abase + t * BK;
        const __half* Wg = Wbase + t * BK;
        __half* sA = sbuf + buf * (2 * BM * LDH);
        __half* sB = sA + BM * LDH;
#pragma unroll
        for (int i = 0; i < 4; ++i) {
            const int idx = tid + (i << 8);
            const int row = idx >> 3;
            const int seg = idx & 7;
            const __half* srcA = Ag + (size_t)row * EE + seg * 8;
            const __half* srcB = Wg + (size_t)row * EE + seg * 8;
            uint32_t dA = (uint32_t)__cvta_generic_to_shared(sA + row * LDH + seg * 8);
            uint32_t dB = (uint32_t)__cvta_generic_to_shared(sB + row * LDH + seg * 8);
            asm volatile("cp.async.cg.shared.global [%0], [%1], 16;" :: "r"(dA), "l"(srcA));
            asm volatile("cp.async.cg.shared.global [%0], [%1], 16;" :: "r"(dB), "l"(srcB));
        }
        asm volatile("cp.async.commit_group;" ::: "memory");
    };

    issue_tile(0, 0);

    const int nT = EE / BK;    // 12
    for (int t = 0; t < nT; ++t) {
        if (t + 1 < nT) {
            issue_tile(t + 1, (t + 1) & 1);
            asm volatile("cp.async.wait_group 1;" ::: "memory");
        } else {
            asm volatile("cp.async.wait_group 0;" ::: "memory");
        }
        __syncthreads();

        const __half* sA = sbuf + (t & 1) * (2 * BM * LDH);
        const __half* sB = sA + BM * LDH;
#pragma unroll
        for (int kk = 0; kk < BK / 16; ++kk) {
            wmma::fragment<wmma::matrix_a, 16, 16, 16, __half, wmma::row_major> af[2];
            wmma::fragment<wmma::matrix_b, 16, 16, 16, __half, wmma::col_major> bf[4];
#pragma unroll
            for (int i = 0; i < 2; ++i)
                wmma::load_matrix_sync(af[i], sA + (warp_m * 32 + i * 16) * LDH + kk * 16, LDH);
#pragma unroll
            for (int j = 0; j < 4; ++j)
                wmma::load_matrix_sync(bf[j], sB + (warp_n * 64 + j * 16) * LDH + kk * 16, LDH);
#pragma unroll
            for (int i = 0; i < 2; ++i)
#pragma unroll
                for (int j = 0; j < 4; ++j)
                    wmma::mma_sync(acc[i][j], af[i], bf[j], acc[i][j]);
        }
        __syncthreads();
    }

#pragma unroll
    for (int i = 0; i < 2; ++i)
#pragma unroll
        for (int j = 0; j < 4; ++j)
            wmma::store_matrix_sync(Cs + (warp_m * 32 + i * 16) * LDS_C + warp_n * 64 + j * 16,
                                    acc[i][j], LDS_C, wmma::mem_row_major);
    __syncthreads();

#pragma unroll
    for (int i = 0; i < 16; ++i) {
        const int fi  = tid + (i << 8);
        const int row = fi >> 5;
        const int col = (fi & 31) * 4;
        const int m = m0 + row;
        const int n = n0 + col;
        float4 o = *(const float4*)(Cs + row * LDS_C + col);
        const float4 bv = *(const float4*)(bias + n);
        o.x += bv.x; o.y += bv.y; o.z += bv.z; o.w += bv.w;
        if (MODE == 0) {
            const int c  = n / EE;
            const int rr = n - c * EE;
            const int h  = rr >> 6;
            const int d  = rr & 63;
            const int b  = m >> 10;
            const int s  = m & 1023;
            if (c == 0) { o.x *= 0.125f; o.y *= 0.125f; o.z *= 0.125f; o.w *= 0.125f; }
            __half* dst = ((c == 0) ? Qo : (c == 1) ? Ko : Vo)
                          + ((((size_t)b * HH + h) * SS + s) * DD + d);
            *(__half2*)(dst)     = __floats2half2_rn(o.x, o.y);
            *(__half2*)(dst + 2) = __floats2half2_rn(o.z, o.w);
        } else {
            *(float4*)(C + (size_t)m * EE + n) = o;
        }
    }
}

// ---------------------------------------------------------------------------
// Flash attention v3: register-resident FA2 with raw mma.sync.m16n8k16.
// (unchanged from R7 — known good)
// ---------------------------------------------------------------------------
#define ATT_SMEM_BYTES ((128 * ATT_LDH + 4 * 64 * ATT_LDH) * 2)

#define MMA16816(C, A, B)                                                      \
    asm volatile("mma.sync.aligned.m16n8k16.row.col.f32.f16.f16.f32 "          \
        "{%0,%1,%2,%3}, {%4,%5,%6,%7}, {%8,%9}, {%0,%1,%2,%3};"                \
        : "+f"((C)[0]), "+f"((C)[1]), "+f"((C)[2]), "+f"((C)[3])               \
        : "r"((A)[0]), "r"((A)[1]), "r"((A)[2]), "r"((A)[3]),                  \
          "r"((B)[0]), "r"((B)[1]))

#define LDMATRIX_X4(R, ADDR)                                                   \
    asm volatile("ldmatrix.sync.aligned.m8n8.x4.shared.b16 {%0,%1,%2,%3}, [%4];" \
        : "=r"((R)[0]), "=r"((R)[1]), "=r"((R)[2]), "=r"((R)[3]) : "r"(ADDR))

#define LDMATRIX_X4_T(R, ADDR)                                                 \
    asm volatile("ldmatrix.sync.aligned.m8n8.x4.trans.shared.b16 {%0,%1,%2,%3}, [%4];" \
        : "=r"((R)[0]), "=r"((R)[1]), "=r"((R)[2]), "=r"((R)[3]) : "r"(ADDR))

__global__ __launch_bounds__(256, 1)
void attn_kernel(const __half* __restrict__ qh, const __half* __restrict__ kh,
                 const __half* __restrict__ vh, __half* __restrict__ ctxh)
{
    extern __shared__ char smraw[];
    __half* sQ  = (__half*)smraw;                        // 128 x 72
    __half* sK0 = sQ + 128 * ATT_LDH;                    // 2 x (64 x 72)
    __half* sV0 = sK0 + 2 * 64 * ATT_LDH;                // 2 x (64 x 72)

    const int tid  = threadIdx.x;
    const int wid  = tid >> 5;
    const int lane = tid & 31;
    const int gid  = lane >> 2;
    const int t4   = lane & 3;
    const int hh   = blockIdx.y;
    const int bb   = blockIdx.z;
    const int bh   = bb * HH + hh;
    const int q0   = blockIdx.x * 128;
    const int len  = g_len[bb];

    if (q0 >= len) {
#pragma unroll
        for (int i = 0; i < 4; ++i) {
            const int idx = tid + (i << 8);
            const int r = idx >> 3, seg = idx & 7;
            *(uint4*)(ctxh + ((size_t)bb * SS + q0 + r) * EE + hh * DD + seg * 8)
                = make_uint4(0u, 0u, 0u, 0u);
        }
        return;
    }

    {
        const uint4* qg = (const uint4*)(qh + ((size_t)bh * SS + q0) * DD);
#pragma unroll
        for (int i = 0; i < 4; ++i) {
            const int idx = tid + (i << 8);
            const int r = idx >> 3, seg = idx & 7;
            *(uint4*)(sQ + r * ATT_LDH + seg * 8) = qg[r * 8 + seg];
        }
    }
    __syncthreads();

    uint32_t qa[4][4];
    {
        const int r  = wid * 16 + (lane & 15);
        const int c8 = (lane >> 4) * 8;
#pragma unroll
        for (int kk = 0; kk < 4; ++kk) {
            uint32_t a = (uint32_t)__cvta_generic_to_shared(sQ + r * ATT_LDH + kk * 16 + c8);
            LDMATRIX_X4(qa[kk], a);
        }
    }

    const uint4* kg = (const uint4*)(kh + (size_t)bh * SS * DD);
    const uint4* vg = (const uint4*)(vh + (size_t)bh * SS * DD);

    auto issue_kv = [&](int j0, int buf) {
        __half* dK = sK0 + buf * (64 * ATT_LDH);
        __half* dV = sV0 + buf * (64 * ATT_LDH);
#pragma unroll
        for (int i = 0; i < 2; ++i) {
            const int idx = tid + (i << 8);
            const int r = idx >> 3, seg = idx & 7;
            const uint4* sk = &kg[(j0 + r) * 8 + seg];
            const uint4* sv = &vg[(j0 + r) * 8 + seg];
            uint32_t aK = (uint32_t)__cvta_generic_to_shared(dK + r * ATT_LDH + seg * 8);
            uint32_t aV = (uint32_t)__cvta_generic_to_shared(dV + r * ATT_LDH + seg * 8);
            asm volatile("cp.async.cg.shared.global [%0], [%1], 16;" :: "r"(aK), "l"(sk));
            asm volatile("cp.async.cg.shared.global [%0], [%1], 16;" :: "r"(aV), "l"(sv));
        }
        asm volatile("cp.async.commit_group;" ::: "memory");
    };

    float oacc[8][4];
#pragma unroll
    for (int i = 0; i < 8; ++i)
#pragma unroll
        for (int j = 0; j < 4; ++j) oacc[i][j] = 0.f;
    float m0r = -1e30f, m1r = -1e30f, l0 = 0.f, l1 = 0.f;

    const int nTiles = (len + 63) >> 6;
    issue_kv(0, 0);

    for (int t = 0; t < nTiles; ++t) {
        const int j0  = t << 6;
        const int buf = t & 1;
        if (t + 1 < nTiles) {
            issue_kv(j0 + 64, buf ^ 1);
            asm volatile("cp.async.wait_group 1;" ::: "memory");
        } else {
            asm volatile("cp.async.wait_group 0;" ::: "memory");
        }
        __syncthreads();

        const __half* sK = sK0 + buf * (64 * ATT_LDH);
        const __half* sV = sV0 + buf * (64 * ATT_LDH);

        float sacc[8][4];
#pragma unroll
        for (int i = 0; i < 8; ++i)
#pragma unroll
            for (int j = 0; j < 4; ++j) sacc[i][j] = 0.f;

        {
            const int rb = ((lane >> 4) & 1) * 8 + (lane & 7);
            const int cb = ((lane >> 3) & 1) * 8;
#pragma unroll
            for (int kk = 0; kk < 4; ++kk) {
#pragma unroll
                for (int jc = 0; jc < 8; jc += 2) {
                    uint32_t kb[4];
                    uint32_t a = (uint32_t)__cvta_generic_to_shared(
                        sK + (jc * 8 + rb) * ATT_LDH + kk * 16 + cb);
                    LDMATRIX_X4(kb, a);
                    MMA16816(sacc[jc],     qa[kk], kb);
                    MMA16816(sacc[jc + 1], qa[kk], kb + 2);
                }
            }
        }

        const int nk = min(64, len - j0);
        if (nk < 64) {
#pragma unroll
            for (int jc = 0; jc < 8; ++jc) {
                const int c = jc * 8 + t4 * 2;
                if (c     >= nk) { sacc[jc][0] = -1e30f; sacc[jc][2] = -1e30f; }
                if (c + 1 >= nk) { sacc[jc][1] = -1e30f; sacc[jc][3] = -1e30f; }
            }
        }
        float mt0 = -1e30f, mt1 = -1e30f;
#pragma unroll
        for (int jc = 0; jc < 8; ++jc) {
            mt0 = fmaxf(mt0, fmaxf(sacc[jc][0], sacc[jc][1]));
            mt1 = fmaxf(mt1, fmaxf(sacc[jc][2], sacc[jc][3]));
        }
        mt0 = fmaxf(mt0, __shfl_xor_sync(0xffffffffu, mt0, 1));
        mt0 = fmaxf(mt0, __shfl_xor_sync(0xffffffffu, mt0, 2));
        mt1 = fmaxf(mt1, __shfl_xor_sync(0xffffffffu, mt1, 1));
        mt1 = fmaxf(mt1, __shfl_xor_sync(0xffffffffu, mt1, 2));

        const float mn0 = fmaxf(m0r, mt0), mn1 = fmaxf(m1r, mt1);
        const float corr0 = __expf(m0r - mn0), corr1 = __expf(m1r - mn1);
        m0r = mn0; m1r = mn1;

        float ls0 = 0.f, ls1 = 0.f;
#pragma unroll
        for (int jc = 0; jc < 8; ++jc) {
            sacc[jc][0] = __expf(sacc[jc][0] - mn0);
            sacc[jc][1] = __expf(sacc[jc][1] - mn0);
            sacc[jc][2] = __expf(sacc[jc][2] - mn1);
            sacc[jc][3] = __expf(sacc[jc][3] - mn1);
            ls0 += sacc[jc][0] + sacc[jc][1];
            ls1 += sacc[jc][2] + sacc[jc][3];
        }
        ls0 += __shfl_xor_sync(0xffffffffu, ls0, 1);
        ls0 += __shfl_xor_sync(0xffffffffu, ls0, 2);
        ls1 += __shfl_xor_sync(0xffffffffu, ls1, 1);
        ls1 += __shfl_xor_sync(0xffffffffu, ls1, 2);
        l0 = l0 * corr0 + ls0;
        l1 = l1 * corr1 + ls1;

#pragma unroll
        for (int nc = 0; nc < 8; ++nc) {
            oacc[nc][0] *= corr0; oacc[nc][1] *= corr0;
            oacc[nc][2] *= corr1; oacc[nc][3] *= corr1;
        }

        {
            const int rb = ((lane >> 3) & 1) * 8 + (lane & 7);
            const int cb = (lane >> 4) * 8;
#pragma unroll
            for (int kk = 0; kk < 4; ++kk) {
                uint32_t pa[4];
                pa[0] = packh2(sacc[2 * kk][0],     sacc[2 * kk][1]);
                pa[1] = packh2(sacc[2 * kk][2],     sacc[2 * kk][3]);
                pa[2] = packh2(sacc[2 * kk + 1][0], sacc[2 * kk + 1][1]);
                pa[3] = packh2(sacc[2 * kk + 1][2], sacc[2 * kk + 1][3]);
#pragma unroll
                for (int nc = 0; nc < 8; nc += 2) {
                    uint32_t vb[4];
                    uint32_t a = (uint32_t)__cvta_generic_to_shared(
                        sV + (kk * 16 + rb) * ATT_LDH + nc * 8 + cb);
                    LDMATRIX_X4_T(vb, a);
                    MMA16816(oacc[nc],     pa, vb);
                    MMA16816(oacc[nc + 1], pa, vb + 2);
                }
            }
        }
        __syncthreads();
    }

    const int qrow0 = q0 + wid * 16 + gid;
    const float fin0 = (qrow0     < len) ? (1.0f / l0) : 0.f;
    const float fin1 = (qrow0 + 8 < len) ? (1.0f / l1) : 0.f;
    __half* base0 = ctxh + ((size_t)bb * SS + qrow0) * EE + hh * DD;
    __half* base1 = base0 + (size_t)8 * EE;
#pragma unroll
    for (int nc = 0; nc < 8; ++nc) {
        const int d = nc * 8 + t4 * 2;
        *(__half2*)(base0 + d) = __floats2half2_rn(oacc[nc][0] * fin0, oacc[nc][1] * fin0);
        *(__half2*)(base1 + d) = __floats2half2_rn(oacc[nc][2] * fin1, oacc[nc][3] * fin1);
    }
}

// ---------------------------------------------------------------------------
// Launch
// ---------------------------------------------------------------------------
extern "C" void kernel_launch(void* const* d_in, const int* in_sizes, int n_in,
                              void* d_out, int out_size)
{
    const float* x            = (const float*)d_in[0];
    const unsigned char* mask = (const unsigned char*)d_in[1];
    const float* Wqkv_w       = (const float*)d_in[2];
    const float* Wqkv_b       = (const float*)d_in[3];
    const float* out_w        = (const float*)d_in[4];
    const float* out_b        = (const float*)d_in[5];
    float* out                = (float*)d_out;

    __half *xh, *wqkvh, *owh, *qh, *kh, *vh, *ctxh;
    cudaGetSymbolAddress((void**)&xh,    g_xh);
    cudaGetSymbolAddress((void**)&wqkvh, g_wqkvh);
    cudaGetSymbolAddress((void**)&owh,   g_owh);
    cudaGetSymbolAddress((void**)&qh,    g_qh);
    cudaGetSymbolAddress((void**)&kh,    g_kh);
    cudaGetSymbolAddress((void**)&vh,    g_vh);
    cudaGetSymbolAddress((void**)&ctxh,  g_ctxh);

    // 1) lengths + fp16 conversions
    lengths_kernel<<<BB, 32>>>(mask);
    conv_kernel<<<(BB * SS * EE / 4 + 255) / 256, 256>>>(x, xh, BB * SS * EE / 4);
    conv_kernel<<<(3 * EE * EE / 4 + 255) / 256, 256>>>(Wqkv_w, wqkvh, 3 * EE * EE / 4);
    conv_kernel<<<(EE * EE / 4 + 255) / 256, 256>>>(out_w, owh, EE * EE / 4);

    // 2) QKV projection (fp16 wmma + cp.async + padded-slab skip)
    cudaFuncSetAttribute(tc_gemm<0>, cudaFuncAttributeMaxDynamicSharedMemorySize, GEMM_SMEM_BYTES);
    cudaFuncSetAttribute(tc_gemm<1>, cudaFuncAttributeMaxDynamicSharedMemorySize, GEMM_SMEM_BYTES);
    {
        dim3 grid(3 * EE / BN, (BB * SS) / BM);
        tc_gemm<0><<<grid, 256, GEMM_SMEM_BYTES>>>(xh, wqkvh, Wqkv_b, nullptr, qh, kh, vh);
    }

    // 3) register-resident flash attention -> ctx fp16 [B,S,E]
    cudaFuncSetAttribute(attn_kernel, cudaFuncAttributeMaxDynamicSharedMemorySize, ATT_SMEM_BYTES);
    attn_kernel<<<dim3(SS / 128, HH, BB), 256, ATT_SMEM_BYTES>>>(qh, kh, vh, ctxh);

    // 4) output projection (fp16 wmma + bias-fill for padded slabs)
    {
        dim3 grid(EE / BN, (BB * SS) / BM);
        tc_gemm<1><<<grid, 256, GEMM_SMEM_BYTES>>>(ctxh, owh, out_b, out, nullptr, nullptr, nullptr);
    }
}

// round 9
// speedup vs baseline: 8.8832x; 1.0278x over previous
#include <cuda_runtime.h>
#include <cuda_fp16.h>
#include <math.h>
#include <stdint.h>

// Problem constants
#define BB 8
#define SS 1024
#define EE 768
#define HH 12
#define DD 64

// GEMM tiling
#define BM 128
#define BN 128
#define BK 64
#define LDH 72            // padded halves stride in smem tiles

// Attention smem stride (halves)
#define ATT_LDH 72

// q pre-scale: 1/sqrt(64) * log2(e)  (softmax runs in exp2 domain)
#define QSCALE (0.125f * 1.4426950408889634f)

// Scratch (allocation-free rule: __device__ globals)
__device__ __half g_xh[(size_t)BB * SS * EE];
__device__ __half g_wqkvh[(size_t)3 * EE * EE];
__device__ __half g_owh[(size_t)EE * EE];
__device__ __half g_qh[(size_t)BB * HH * SS * DD];
__device__ __half g_kh[(size_t)BB * HH * SS * DD];
__device__ __half g_vh[(size_t)BB * HH * SS * DD];
__device__ __half g_ctxh[(size_t)BB * SS * EE];
__device__ int    g_len[BB];

__device__ __forceinline__ uint32_t packh2(float a, float b) {
    __half2 h = __floats2half2_rn(a, b);
    return *(uint32_t*)&h;
}

#define MMA16816(C, A, B)                                                      \
    asm volatile("mma.sync.aligned.m16n8k16.row.col.f32.f16.f16.f32 "          \
        "{%0,%1,%2,%3}, {%4,%5,%6,%7}, {%8,%9}, {%0,%1,%2,%3};"                \
        : "+f"((C)[0]), "+f"((C)[1]), "+f"((C)[2]), "+f"((C)[3])               \
        : "r"((A)[0]), "r"((A)[1]), "r"((A)[2]), "r"((A)[3]),                  \
          "r"((B)[0]), "r"((B)[1]))

#define LDMATRIX_X4(R, ADDR)                                                   \
    asm volatile("ldmatrix.sync.aligned.m8n8.x4.shared.b16 {%0,%1,%2,%3}, [%4];" \
        : "=r"((R)[0]), "=r"((R)[1]), "=r"((R)[2]), "=r"((R)[3]) : "r"(ADDR))

#define LDMATRIX_X4_T(R, ADDR)                                                 \
    asm volatile("ldmatrix.sync.aligned.m8n8.x4.trans.shared.b16 {%0,%1,%2,%3}, [%4];" \
        : "=r"((R)[0]), "=r"((R)[1]), "=r"((R)[2]), "=r"((R)[3]) : "r"(ADDR))

// ---------------------------------------------------------------------------
// fp32 -> fp16 conversion (RN)
// ---------------------------------------------------------------------------
__global__ void conv_kernel(const float* __restrict__ src, __half* __restrict__ dst, int n4)
{
    const int i = blockIdx.x * 256 + threadIdx.x;
    if (i < n4) {
        const float4 v = ((const float4*)src)[i];
        ((__half2*)dst)[i * 2]     = __floats2half2_rn(v.x, v.y);
        ((__half2*)dst)[i * 2 + 1] = __floats2half2_rn(v.z, v.w);
    }
}

// ---------------------------------------------------------------------------
// Mask -> per-batch valid length (prefix mask; count nonzeros).
// ---------------------------------------------------------------------------
__global__ void lengths_kernel(const unsigned char* __restrict__ mask)
{
    const int b = blockIdx.x;
    const int lane = threadIdx.x;
    int cnt = 0;
    if (mask[1] != 0) {
        const unsigned char* row = mask + (size_t)b * SS;
        for (int i = lane; i < SS; i += 32) cnt += (row[i] != 0);
    } else {
        const unsigned int* row = (const unsigned int*)mask + (size_t)b * SS;
        for (int i = lane; i < SS; i += 32) cnt += (row[i] != 0u);
    }
#pragma unroll
    for (int o = 16; o; o >>= 1) cnt += __shfl_xor_sync(0xffffffffu, cnt, o);
    if (lane == 0) g_len[b] = cnt;
}

// ---------------------------------------------------------------------------
// fp16 GEMM via raw mma.sync + ldmatrix: C[m,n] = sum_k A[m,k]*W[n,k] + bias[n]
// CTA 128x128, BK=64, 256 thr (8 warps, 4m x 2n), warp tile 32x64.
// cp.async double-buffered. Fragment epilogue writes straight to global.
// MODE 0: scatter q/k/v fp16 (q scaled by QSCALE). MODE 1: fp32 C.
// Padded-slab fast paths as in R8.
// ---------------------------------------------------------------------------
#define GEMM_SMEM_BYTES (2 * 2 * BM * LDH * 2)

template <int MODE>
__global__ __launch_bounds__(256, 2)
void tc_gemm(const __half* __restrict__ A, const __half* __restrict__ W,
             const float* __restrict__ bias, float* __restrict__ C,
             __half* __restrict__ Qo, __half* __restrict__ Ko, __half* __restrict__ Vo)
{
    extern __shared__ char smraw[];
    __half* sbuf = (__half*)smraw;

    const int tid    = threadIdx.x;
    const int wid    = tid >> 5;
    const int lane   = tid & 31;
    const int warp_m = wid & 3;
    const int warp_n = wid >> 2;
    const int m0     = blockIdx.y * BM;
    const int n0     = blockIdx.x * BN;

    // ---- padded-slab fast paths
    const int len = g_len[m0 >> 10];
    if ((m0 & 1023) >= len) {
        if (MODE == 0) return;
        for (int idx = tid; idx < BM * (EE / 4); idx += 256) {
            const int row = idx / (EE / 4);
            const int c4  = idx % (EE / 4);
            *(float4*)(C + (size_t)(m0 + row) * EE + c4 * 4) =
                *(const float4*)(bias + c4 * 4);
        }
        return;
    }

    const __half* Abase = A + (size_t)m0 * EE;
    const __half* Wbase = W + (size_t)n0 * EE;

    float acc[2][8][4];
#pragma unroll
    for (int i = 0; i < 2; ++i)
#pragma unroll
        for (int j = 0; j < 8; ++j)
#pragma unroll
            for (int r = 0; r < 4; ++r) acc[i][j][r] = 0.f;

    auto issue_tile = [&](int t, int buf) {
        const __half* Ag = Abase + t * BK;
        const __half* Wg = Wbase + t * BK;
        __half* sA = sbuf + buf * (2 * BM * LDH);
        __half* sB = sA + BM * LDH;
#pragma unroll
        for (int i = 0; i < 4; ++i) {
            const int idx = tid + (i << 8);
            const int row = idx >> 3;
            const int seg = idx & 7;
            const __half* srcA = Ag + (size_t)row * EE + seg * 8;
            const __half* srcB = Wg + (size_t)row * EE + seg * 8;
            uint32_t dA = (uint32_t)__cvta_generic_to_shared(sA + row * LDH + seg * 8);
            uint32_t dB = (uint32_t)__cvta_generic_to_shared(sB + row * LDH + seg * 8);
            asm volatile("cp.async.cg.shared.global [%0], [%1], 16;" :: "r"(dA), "l"(srcA));
            asm volatile("cp.async.cg.shared.global [%0], [%1], 16;" :: "r"(dB), "l"(srcB));
        }
        asm volatile("cp.async.commit_group;" ::: "memory");
    };

    issue_tile(0, 0);

    // ldmatrix lane addressing (same pattern as attention kernel)
    const int ar  = lane & 15;               // A: row within 16
    const int ac8 = (lane >> 4) * 8;         // A: col quadrant
    const int br  = ((lane >> 4) & 1) * 8 + (lane & 7);   // B: row pattern
    const int bc8 = ((lane >> 3) & 1) * 8;                // B: col quadrant

    const int nT = EE / BK;    // 12
    for (int t = 0; t < nT; ++t) {
        if (t + 1 < nT) {
            issue_tile(t + 1, (t + 1) & 1);
            asm volatile("cp.async.wait_group 1;" ::: "memory");
        } else {
            asm volatile("cp.async.wait_group 0;" ::: "memory");
        }
        __syncthreads();

        const __half* sA = sbuf + (t & 1) * (2 * BM * LDH);
        const __half* sB = sA + BM * LDH;
#pragma unroll
        for (int kk = 0; kk < BK / 16; ++kk) {
            uint32_t af[2][4];
#pragma unroll
            for (int i = 0; i < 2; ++i) {
                uint32_t a = (uint32_t)__cvta_generic_to_shared(
                    sA + (warp_m * 32 + i * 16 + ar) * LDH + kk * 16 + ac8);
                LDMATRIX_X4(af[i], a);
            }
#pragma unroll
            for (int jc = 0; jc < 8; jc += 2) {
                uint32_t kb[4];
                uint32_t a = (uint32_t)__cvta_generic_to_shared(
                    sB + (warp_n * 64 + jc * 8 + br) * LDH + kk * 16 + bc8);
                LDMATRIX_X4(kb, a);
#pragma unroll
                for (int i = 0; i < 2; ++i) {
                    MMA16816(acc[i][jc],     af[i], kb);
                    MMA16816(acc[i][jc + 1], af[i], kb + 2);
                }
            }
        }
        __syncthreads();
    }

    // ---- fragment epilogue: direct global stores, bias from registers
    const int gid = lane >> 2;      // row within 8-group
    const int t4  = lane & 3;       // 2-col group
#pragma unroll
    for (int i = 0; i < 2; ++i) {
        const int mrow = m0 + warp_m * 32 + i * 16 + gid;   // rows mrow, mrow+8
#pragma unroll
        for (int jc = 0; jc < 8; ++jc) {
            const int n = n0 + warp_n * 64 + jc * 8 + t4 * 2;
            const float2 bv = *(const float2*)(bias + n);
            float ox0 = acc[i][jc][0] + bv.x, oy0 = acc[i][jc][1] + bv.y;
            float ox1 = acc[i][jc][2] + bv.x, oy1 = acc[i][jc][3] + bv.y;
            if (MODE == 0) {
                const int c  = n / EE;
                const int rr = n - c * EE;
                const int h  = rr >> 6;
                const int d  = rr & 63;
                if (c == 0) { ox0 *= QSCALE; oy0 *= QSCALE; ox1 *= QSCALE; oy1 *= QSCALE; }
                __half* dst = ((c == 0) ? Qo : (c == 1) ? Ko : Vo);
                const int b = mrow >> 10;
                const int s = mrow & 1023;
                __half* p0 = dst + ((((size_t)b * HH + h) * SS + s) * DD + d);
                *(__half2*)p0                      = __floats2half2_rn(ox0, oy0);
                *(__half2*)(p0 + (size_t)8 * DD)   = __floats2half2_rn(ox1, oy1);
            } else {
                *(float2*)(C + (size_t)mrow * EE + n)       = make_float2(ox0, oy0);
                *(float2*)(C + (size_t)(mrow + 8) * EE + n) = make_float2(ox1, oy1);
            }
        }
    }
}

// ---------------------------------------------------------------------------
// Flash attention v4: register-resident FA2, exp2-domain softmax.
// Q pre-scaled by 0.125*log2(e); probabilities via exp2f (bare MUFU).
// Early-exit for padded q-blocks writes nothing (gemm1 never reads them).
// ---------------------------------------------------------------------------
#define ATT_SMEM_BYTES ((128 * ATT_LDH + 4 * 64 * ATT_LDH) * 2)

__global__ __launch_bounds__(256, 1)
void attn_kernel(const __half* __restrict__ qh, const __half* __restrict__ kh,
                 const __half* __restrict__ vh, __half* __restrict__ ctxh)
{
    extern __shared__ char smraw[];
    __half* sQ  = (__half*)smraw;                        // 128 x 72
    __half* sK0 = sQ + 128 * ATT_LDH;                    // 2 x (64 x 72)
    __half* sV0 = sK0 + 2 * 64 * ATT_LDH;                // 2 x (64 x 72)

    const int tid  = threadIdx.x;
    const int wid  = tid >> 5;
    const int lane = tid & 31;
    const int gid  = lane >> 2;
    const int t4   = lane & 3;
    const int hh   = blockIdx.y;
    const int bb   = blockIdx.z;
    const int bh   = bb * HH + hh;
    const int q0   = blockIdx.x * 128;
    const int len  = g_len[bb];

    // fully-padded q-block: gemm1's bias-fill path never reads these ctx rows
    if (q0 >= len) return;

    {
        const uint4* qg = (const uint4*)(qh + ((size_t)bh * SS + q0) * DD);
#pragma unroll
        for (int i = 0; i < 4; ++i) {
            const int idx = tid + (i << 8);
            const int r = idx >> 3, seg = idx & 7;
            *(uint4*)(sQ + r * ATT_LDH + seg * 8) = qg[r * 8 + seg];
        }
    }
    __syncthreads();

    uint32_t qa[4][4];
    {
        const int r  = wid * 16 + (lane & 15);
        const int c8 = (lane >> 4) * 8;
#pragma unroll
        for (int kk = 0; kk < 4; ++kk) {
            uint32_t a = (uint32_t)__cvta_generic_to_shared(sQ + r * ATT_LDH + kk * 16 + c8);
            LDMATRIX_X4(qa[kk], a);
        }
    }

    const uint4* kg = (const uint4*)(kh + (size_t)bh * SS * DD);
    const uint4* vg = (const uint4*)(vh + (size_t)bh * SS * DD);

    auto issue_kv = [&](int j0, int buf) {
        __half* dK = sK0 + buf * (64 * ATT_LDH);
        __half* dV = sV0 + buf * (64 * ATT_LDH);
#pragma unroll
        for (int i = 0; i < 2; ++i) {
            const int idx = tid + (i << 8);
            const int r = idx >> 3, seg = idx & 7;
            const uint4* sk = &kg[(j0 + r) * 8 + seg];
            const uint4* sv = &vg[(j0 + r) * 8 + seg];
            uint32_t aK = (uint32_t)__cvta_generic_to_shared(dK + r * ATT_LDH + seg * 8);
            uint32_t aV = (uint32_t)__cvta_generic_to_shared(dV + r * ATT_LDH + seg * 8);
            asm volatile("cp.async.cg.shared.global [%0], [%1], 16;" :: "r"(aK), "l"(sk));
            asm volatile("cp.async.cg.shared.global [%0], [%1], 16;" :: "r"(aV), "l"(sv));
        }
        asm volatile("cp.async.commit_group;" ::: "memory");
    };

    float oacc[8][4];
#pragma unroll
    for (int i = 0; i < 8; ++i)
#pragma unroll
        for (int j = 0; j < 4; ++j) oacc[i][j] = 0.f;
    float m0r = -1e30f, m1r = -1e30f, l0 = 0.f, l1 = 0.f;

    const int nTiles = (len + 63) >> 6;
    issue_kv(0, 0);

    for (int t = 0; t < nTiles; ++t) {
        const int j0  = t << 6;
        const int buf = t & 1;
        if (t + 1 < nTiles) {
            issue_kv(j0 + 64, buf ^ 1);
            asm volatile("cp.async.wait_group 1;" ::: "memory");
        } else {
            asm volatile("cp.async.wait_group 0;" ::: "memory");
        }
        __syncthreads();

        const __half* sK = sK0 + buf * (64 * ATT_LDH);
        const __half* sV = sV0 + buf * (64 * ATT_LDH);

        float sacc[8][4];
#pragma unroll
        for (int i = 0; i < 8; ++i)
#pragma unroll
            for (int j = 0; j < 4; ++j) sacc[i][j] = 0.f;

        {
            const int rb = ((lane >> 4) & 1) * 8 + (lane & 7);
            const int cb = ((lane >> 3) & 1) * 8;
#pragma unroll
            for (int kk = 0; kk < 4; ++kk) {
#pragma unroll
                for (int jc = 0; jc < 8; jc += 2) {
                    uint32_t kb[4];
                    uint32_t a = (uint32_t)__cvta_generic_to_shared(
                        sK + (jc * 8 + rb) * ATT_LDH + kk * 16 + cb);
                    LDMATRIX_X4(kb, a);
                    MMA16816(sacc[jc],     qa[kk], kb);
                    MMA16816(sacc[jc + 1], qa[kk], kb + 2);
                }
            }
        }

        const int nk = min(64, len - j0);
        if (nk < 64) {
#pragma unroll
            for (int jc = 0; jc < 8; ++jc) {
                const int c = jc * 8 + t4 * 2;
                if (c     >= nk) { sacc[jc][0] = -1e30f; sacc[jc][2] = -1e30f; }
                if (c + 1 >= nk) { sacc[jc][1] = -1e30f; sacc[jc][3] = -1e30f; }
            }
        }
        float mt0 = -1e30f, mt1 = -1e30f;
#pragma unroll
        for (int jc = 0; jc < 8; ++jc) {
            mt0 = fmaxf(mt0, fmaxf(sacc[jc][0], sacc[jc][1]));
            mt1 = fmaxf(mt1, fmaxf(sacc[jc][2], sacc[jc][3]));
        }
        mt0 = fmaxf(mt0, __shfl_xor_sync(0xffffffffu, mt0, 1));
        mt0 = fmaxf(mt0, __shfl_xor_sync(0xffffffffu, mt0, 2));
        mt1 = fmaxf(mt1, __shfl_xor_sync(0xffffffffu, mt1, 1));
        mt1 = fmaxf(mt1, __shfl_xor_sync(0xffffffffu, mt1, 2));

        const float mn0 = fmaxf(m0r, mt0), mn1 = fmaxf(m1r, mt1);
        const float corr0 = exp2f(m0r - mn0), corr1 = exp2f(m1r - mn1);
        m0r = mn0; m1r = mn1;

        float ls0 = 0.f, ls1 = 0.f;
#pragma unroll
        for (int jc = 0; jc < 8; ++jc) {
            sacc[jc][0] = exp2f(sacc[jc][0] - mn0);
            sacc[jc][1] = exp2f(sacc[jc][1] - mn0);
            sacc[jc][2] = exp2f(sacc[jc][2] - mn1);
            sacc[jc][3] = exp2f(sacc[jc][3] - mn1);
            ls0 += sacc[jc][0] + sacc[jc][1];
            ls1 += sacc[jc][2] + sacc[jc][3];
        }
        ls0 += __shfl_xor_sync(0xffffffffu, ls0, 1);
        ls0 += __shfl_xor_sync(0xffffffffu, ls0, 2);
        ls1 += __shfl_xor_sync(0xffffffffu, ls1, 1);
        ls1 += __shfl_xor_sync(0xffffffffu, ls1, 2);
        l0 = l0 * corr0 + ls0;
        l1 = l1 * corr1 + ls1;

#pragma unroll
        for (int nc = 0; nc < 8; ++nc) {
            oacc[nc][0] *= corr0; oacc[nc][1] *= corr0;
            oacc[nc][2] *= corr1; oacc[nc][3] *= corr1;
        }

        {
            const int rb = ((lane >> 3) & 1) * 8 + (lane & 7);
            const int cb = (lane >> 4) * 8;
#pragma unroll
            for (int kk = 0; kk < 4; ++kk) {
                uint32_t pa[4];
                pa[0] = packh2(sacc[2 * kk][0],     sacc[2 * kk][1]);
                pa[1] = packh2(sacc[2 * kk][2],     sacc[2 * kk][3]);
                pa[2] = packh2(sacc[2 * kk + 1][0], sacc[2 * kk + 1][1]);
                pa[3] = packh2(sacc[2 * kk + 1][2], sacc[2 * kk + 1][3]);
#pragma unroll
                for (int nc = 0; nc < 8; nc += 2) {
                    uint32_t vb[4];
                    uint32_t a = (uint32_t)__cvta_generic_to_shared(
                        sV + (kk * 16 + rb) * ATT_LDH + nc * 8 + cb);
                    LDMATRIX_X4_T(vb, a);
                    MMA16816(oacc[nc],     pa, vb);
                    MMA16816(oacc[nc + 1], pa, vb + 2);
                }
            }
        }
        __syncthreads();
    }

    const int qrow0 = q0 + wid * 16 + gid;
    const float fin0 = (qrow0     < len) ? (1.0f / l0) : 0.f;
    const float fin1 = (qrow0 + 8 < len) ? (1.0f / l1) : 0.f;
    __half* base0 = ctxh + ((size_t)bb * SS + qrow0) * EE + hh * DD;
    __half* base1 = base0 + (size_t)8 * EE;
#pragma unroll
    for (int nc = 0; nc < 8; ++nc) {
        const int d = nc * 8 + t4 * 2;
        *(__half2*)(base0 + d) = __floats2half2_rn(oacc[nc][0] * fin0, oacc[nc][1] * fin0);
        *(__half2*)(base1 + d) = __floats2half2_rn(oacc[nc][2] * fin1, oacc[nc][3] * fin1);
    }
}

// ---------------------------------------------------------------------------
// Launch
// ---------------------------------------------------------------------------
extern "C" void kernel_launch(void* const* d_in, const int* in_sizes, int n_in,
                              void* d_out, int out_size)
{
    const float* x            = (const float*)d_in[0];
    const unsigned char* mask = (const unsigned char*)d_in[1];
    const float* Wqkv_w       = (const float*)d_in[2];
    const float* Wqkv_b       = (const float*)d_in[3];
    const float* out_w        = (const float*)d_in[4];
    const float* out_b        = (const float*)d_in[5];
    float* out                = (float*)d_out;

    __half *xh, *wqkvh, *owh, *qh, *kh, *vh, *ctxh;
    cudaGetSymbolAddress((void**)&xh,    g_xh);
    cudaGetSymbolAddress((void**)&wqkvh, g_wqkvh);
    cudaGetSymbolAddress((void**)&owh,   g_owh);
    cudaGetSymbolAddress((void**)&qh,    g_qh);
    cudaGetSymbolAddress((void**)&kh,    g_kh);
    cudaGetSymbolAddress((void**)&vh,    g_vh);
    cudaGetSymbolAddress((void**)&ctxh,  g_ctxh);

    // 1) lengths + fp16 conversions
    lengths_kernel<<<BB, 32>>>(mask);
    conv_kernel<<<(BB * SS * EE / 4 + 255) / 256, 256>>>(x, xh, BB * SS * EE / 4);
    conv_kernel<<<(3 * EE * EE / 4 + 255) / 256, 256>>>(Wqkv_w, wqkvh, 3 * EE * EE / 4);
    conv_kernel<<<(EE * EE / 4 + 255) / 256, 256>>>(out_w, owh, EE * EE / 4);

    // 2) QKV projection (mma.sync + ldmatrix + cp.async + padded-slab skip)
    cudaFuncSetAttribute(tc_gemm<0>, cudaFuncAttributeMaxDynamicSharedMemorySize, GEMM_SMEM_BYTES);
    cudaFuncSetAttribute(tc_gemm<1>, cudaFuncAttributeMaxDynamicSharedMemorySize, GEMM_SMEM_BYTES);
    {
        dim3 grid(3 * EE / BN, (BB * SS) / BM);
        tc_gemm<0><<<grid, 256, GEMM_SMEM_BYTES>>>(xh, wqkvh, Wqkv_b, nullptr, qh, kh, vh);
    }

    // 3) register-resident flash attention (exp2 domain) -> ctx fp16
    cudaFuncSetAttribute(attn_kernel, cudaFuncAttributeMaxDynamicSharedMemorySize, ATT_SMEM_BYTES);
    attn_kernel<<<dim3(SS / 128, HH, BB), 256, ATT_SMEM_BYTES>>>(qh, kh, vh, ctxh);

    // 4) output projection (mma.sync + bias-fill for padded slabs)
    {
        dim3 grid(EE / BN, (BB * SS) / BM);
        tc_gemm<1><<<grid, 256, GEMM_SMEM_BYTES>>>(ctxh, owh, out_b, out, nullptr, nullptr, nullptr);
    }
}

// round 10
// speedup vs baseline: 9.6752x; 1.0892x over previous
#include <cuda_runtime.h>
#include <cuda_fp16.h>
#include <math.h>
#include <stdint.h>

// Problem constants
#define BB 8
#define SS 1024
#define EE 768
#define HH 12
#define DD 64

// GEMM tiling
#define BM 128
#define BN 128
#define BK 64
#define LDH 72            // padded halves stride in smem tiles

// Attention smem stride (halves)
#define ATT_LDH 72

// q pre-scale: 1/sqrt(64) * log2(e)  (softmax runs in exp2 domain)
#define QSCALE (0.125f * 1.4426950408889634f)

// Scratch (allocation-free rule: __device__ globals)
__device__ __half g_xh[(size_t)BB * SS * EE];
__device__ __half g_wqkvh[(size_t)3 * EE * EE];
__device__ __half g_owh[(size_t)EE * EE];
__device__ __half g_qh[(size_t)BB * HH * SS * DD];
__device__ __half g_kh[(size_t)BB * HH * SS * DD];
__device__ __half g_vh[(size_t)BB * HH * SS * DD];
__device__ __half g_ctxh[(size_t)BB * SS * EE];
__device__ int    g_len[BB];

__device__ __forceinline__ uint32_t packh2(float a, float b) {
    __half2 h = __floats2half2_rn(a, b);
    return *(uint32_t*)&h;
}

#define MMA16816(C, A, B)                                                      \
    asm volatile("mma.sync.aligned.m16n8k16.row.col.f32.f16.f16.f32 "          \
        "{%0,%1,%2,%3}, {%4,%5,%6,%7}, {%8,%9}, {%0,%1,%2,%3};"                \
        : "+f"((C)[0]), "+f"((C)[1]), "+f"((C)[2]), "+f"((C)[3])               \
        : "r"((A)[0]), "r"((A)[1]), "r"((A)[2]), "r"((A)[3]),                  \
          "r"((B)[0]), "r"((B)[1]))

#define LDMATRIX_X4(R, ADDR)                                                   \
    asm volatile("ldmatrix.sync.aligned.m8n8.x4.shared.b16 {%0,%1,%2,%3}, [%4];" \
        : "=r"((R)[0]), "=r"((R)[1]), "=r"((R)[2]), "=r"((R)[3]) : "r"(ADDR))

#define LDMATRIX_X4_T(R, ADDR)                                                 \
    asm volatile("ldmatrix.sync.aligned.m8n8.x4.trans.shared.b16 {%0,%1,%2,%3}, [%4];" \
        : "=r"((R)[0]), "=r"((R)[1]), "=r"((R)[2]), "=r"((R)[3]) : "r"(ADDR))

// ---------------------------------------------------------------------------
// Fused fp32 -> fp16 conversion for x, Wqkv_w, out_w (one launch)
// ---------------------------------------------------------------------------
#define CN1 (BB * SS * EE / 4)
#define CN2 (3 * EE * EE / 4)
#define CN3 (EE * EE / 4)

__global__ void conv_all(const float* __restrict__ x, const float* __restrict__ w1,
                         const float* __restrict__ w2)
{
    int i = blockIdx.x * 256 + threadIdx.x;
    const float* src;
    __half* dst;
    if (i < CN1)              { src = x;  dst = g_xh; }
    else if (i < CN1 + CN2)   { src = w1; dst = g_wqkvh; i -= CN1; }
    else if (i < CN1+CN2+CN3) { src = w2; dst = g_owh;   i -= CN1 + CN2; }
    else return;
    const float4 v = ((const float4*)src)[i];
    ((__half2*)dst)[i * 2]     = __floats2half2_rn(v.x, v.y);
    ((__half2*)dst)[i * 2 + 1] = __floats2half2_rn(v.z, v.w);
}

// ---------------------------------------------------------------------------
// Mask -> per-batch valid length (prefix mask; count nonzeros).
// ---------------------------------------------------------------------------
__global__ void lengths_kernel(const unsigned char* __restrict__ mask)
{
    const int b = blockIdx.x;
    const int lane = threadIdx.x;
    int cnt = 0;
    if (mask[1] != 0) {
        const unsigned char* row = mask + (size_t)b * SS;
        for (int i = lane; i < SS; i += 32) cnt += (row[i] != 0);
    } else {
        const unsigned int* row = (const unsigned int*)mask + (size_t)b * SS;
        for (int i = lane; i < SS; i += 32) cnt += (row[i] != 0u);
    }
#pragma unroll
    for (int o = 16; o; o >>= 1) cnt += __shfl_xor_sync(0xffffffffu, cnt, o);
    if (lane == 0) g_len[b] = cnt;
}

// ---------------------------------------------------------------------------
// fp16 GEMM via raw mma.sync + ldmatrix (unchanged from R9 — known good).
// ---------------------------------------------------------------------------
#define GEMM_SMEM_BYTES (2 * 2 * BM * LDH * 2)

template <int MODE>
__global__ __launch_bounds__(256, 2)
void tc_gemm(const __half* __restrict__ A, const __half* __restrict__ W,
             const float* __restrict__ bias, float* __restrict__ C,
             __half* __restrict__ Qo, __half* __restrict__ Ko, __half* __restrict__ Vo)
{
    extern __shared__ char smraw[];
    __half* sbuf = (__half*)smraw;

    const int tid    = threadIdx.x;
    const int wid    = tid >> 5;
    const int lane   = tid & 31;
    const int warp_m = wid & 3;
    const int warp_n = wid >> 2;
    const int m0     = blockIdx.y * BM;
    const int n0     = blockIdx.x * BN;

    const int len = g_len[m0 >> 10];
    if ((m0 & 1023) >= len) {
        if (MODE == 0) return;
        for (int idx = tid; idx < BM * (EE / 4); idx += 256) {
            const int row = idx / (EE / 4);
            const int c4  = idx % (EE / 4);
            *(float4*)(C + (size_t)(m0 + row) * EE + c4 * 4) =
                *(const float4*)(bias + c4 * 4);
        }
        return;
    }

    const __half* Abase = A + (size_t)m0 * EE;
    const __half* Wbase = W + (size_t)n0 * EE;

    float acc[2][8][4];
#pragma unroll
    for (int i = 0; i < 2; ++i)
#pragma unroll
        for (int j = 0; j < 8; ++j)
#pragma unroll
            for (int r = 0; r < 4; ++r) acc[i][j][r] = 0.f;

    auto issue_tile = [&](int t, int buf) {
        const __half* Ag = Abase + t * BK;
        const __half* Wg = Wbase + t * BK;
        __half* sA = sbuf + buf * (2 * BM * LDH);
        __half* sB = sA + BM * LDH;
#pragma unroll
        for (int i = 0; i < 4; ++i) {
            const int idx = tid + (i << 8);
            const int row = idx >> 3;
            const int seg = idx & 7;
            const __half* srcA = Ag + (size_t)row * EE + seg * 8;
            const __half* srcB = Wg + (size_t)row * EE + seg * 8;
            uint32_t dA = (uint32_t)__cvta_generic_to_shared(sA + row * LDH + seg * 8);
            uint32_t dB = (uint32_t)__cvta_generic_to_shared(sB + row * LDH + seg * 8);
            asm volatile("cp.async.cg.shared.global [%0], [%1], 16;" :: "r"(dA), "l"(srcA));
            asm volatile("cp.async.cg.shared.global [%0], [%1], 16;" :: "r"(dB), "l"(srcB));
        }
        asm volatile("cp.async.commit_group;" ::: "memory");
    };

    issue_tile(0, 0);

    const int ar  = lane & 15;
    const int ac8 = (lane >> 4) * 8;
    const int br  = ((lane >> 4) & 1) * 8 + (lane & 7);
    const int bc8 = ((lane >> 3) & 1) * 8;

    const int nT = EE / BK;    // 12
    for (int t = 0; t < nT; ++t) {
        if (t + 1 < nT) {
            issue_tile(t + 1, (t + 1) & 1);
            asm volatile("cp.async.wait_group 1;" ::: "memory");
        } else {
            asm volatile("cp.async.wait_group 0;" ::: "memory");
        }
        __syncthreads();

        const __half* sA = sbuf + (t & 1) * (2 * BM * LDH);
        const __half* sB = sA + BM * LDH;
#pragma unroll
        for (int kk = 0; kk < BK / 16; ++kk) {
            uint32_t af[2][4];
#pragma unroll
            for (int i = 0; i < 2; ++i) {
                uint32_t a = (uint32_t)__cvta_generic_to_shared(
                    sA + (warp_m * 32 + i * 16 + ar) * LDH + kk * 16 + ac8);
                LDMATRIX_X4(af[i], a);
            }
#pragma unroll
            for (int jc = 0; jc < 8; jc += 2) {
                uint32_t kb[4];
                uint32_t a = (uint32_t)__cvta_generic_to_shared(
                    sB + (warp_n * 64 + jc * 8 + br) * LDH + kk * 16 + bc8);
                LDMATRIX_X4(kb, a);
#pragma unroll
                for (int i = 0; i < 2; ++i) {
                    MMA16816(acc[i][jc],     af[i], kb);
                    MMA16816(acc[i][jc + 1], af[i], kb + 2);
                }
            }
        }
        __syncthreads();
    }

    const int gid = lane >> 2;
    const int t4  = lane & 3;
#pragma unroll
    for (int i = 0; i < 2; ++i) {
        const int mrow = m0 + warp_m * 32 + i * 16 + gid;
#pragma unroll
        for (int jc = 0; jc < 8; ++jc) {
            const int n = n0 + warp_n * 64 + jc * 8 + t4 * 2;
            const float2 bv = *(const float2*)(bias + n);
            float ox0 = acc[i][jc][0] + bv.x, oy0 = acc[i][jc][1] + bv.y;
            float ox1 = acc[i][jc][2] + bv.x, oy1 = acc[i][jc][3] + bv.y;
            if (MODE == 0) {
                const int c  = n / EE;
                const int rr = n - c * EE;
                const int h  = rr >> 6;
                const int d  = rr & 63;
                if (c == 0) { ox0 *= QSCALE; oy0 *= QSCALE; ox1 *= QSCALE; oy1 *= QSCALE; }
                __half* dst = ((c == 0) ? Qo : (c == 1) ? Ko : Vo);
                const int b = mrow >> 10;
                const int s = mrow & 1023;
                __half* p0 = dst + ((((size_t)b * HH + h) * SS + s) * DD + d);
                *(__half2*)p0                      = __floats2half2_rn(ox0, oy0);
                *(__half2*)(p0 + (size_t)8 * DD)   = __floats2half2_rn(ox1, oy1);
            } else {
                *(float2*)(C + (size_t)mrow * EE + n)       = make_float2(ox0, oy0);
                *(float2*)(C + (size_t)(mrow + 8) * EE + n) = make_float2(ox1, oy1);
            }
        }
    }
}

// ---------------------------------------------------------------------------
// Flash attention v5: register-resident FA2, exp2 softmax,
// 3-stage K/V ring with ONE __syncthreads per tile, 2 CTAs/SM.
// smem: sQ 128x72 | sK 3x(64x72) | sV 3x(64x72) = 72 KB
// ---------------------------------------------------------------------------
#define ATT_SMEM_BYTES ((128 * ATT_LDH + 6 * 64 * ATT_LDH) * 2)

__global__ __launch_bounds__(256, 2)
void attn_kernel(const __half* __restrict__ qh, const __half* __restrict__ kh,
                 const __half* __restrict__ vh, __half* __restrict__ ctxh)
{
    extern __shared__ char smraw[];
    __half* sQ  = (__half*)smraw;                        // 128 x 72
    __half* sK0 = sQ + 128 * ATT_LDH;                    // 3 x (64 x 72)
    __half* sV0 = sK0 + 3 * 64 * ATT_LDH;                // 3 x (64 x 72)

    const int tid  = threadIdx.x;
    const int wid  = tid >> 5;
    const int lane = tid & 31;
    const int gid  = lane >> 2;
    const int t4   = lane & 3;
    const int hh   = blockIdx.y;
    const int bb   = blockIdx.z;
    const int bh   = bb * HH + hh;
    const int q0   = blockIdx.x * 128;
    const int len  = g_len[bb];

    if (q0 >= len) return;   // gemm1's bias-fill never reads these ctx rows

    const uint4* kg = (const uint4*)(kh + (size_t)bh * SS * DD);
    const uint4* vg = (const uint4*)(vh + (size_t)bh * SS * DD);

    auto issue_kv = [&](int j0, int buf) {
        __half* dK = sK0 + buf * (64 * ATT_LDH);
        __half* dV = sV0 + buf * (64 * ATT_LDH);
#pragma unroll
        for (int i = 0; i < 2; ++i) {
            const int idx = tid + (i << 8);
            const int r = idx >> 3, seg = idx & 7;
            const uint4* sk = &kg[(j0 + r) * 8 + seg];
            const uint4* sv = &vg[(j0 + r) * 8 + seg];
            uint32_t aK = (uint32_t)__cvta_generic_to_shared(dK + r * ATT_LDH + seg * 8);
            uint32_t aV = (uint32_t)__cvta_generic_to_shared(dV + r * ATT_LDH + seg * 8);
            asm volatile("cp.async.cg.shared.global [%0], [%1], 16;" :: "r"(aK), "l"(sk));
            asm volatile("cp.async.cg.shared.global [%0], [%1], 16;" :: "r"(aV), "l"(sv));
        }
        asm volatile("cp.async.commit_group;" ::: "memory");
    };

    const int nTiles = (len + 63) >> 6;

    // prologue: 2 groups in flight (real or empty, keeps wait-count invariant)
    issue_kv(0, 0);
    if (nTiles > 1) issue_kv(64, 1);
    else            asm volatile("cp.async.commit_group;" ::: "memory");

    // stage Q while tile 0 is in flight
    {
        const uint4* qg = (const uint4*)(qh + ((size_t)bh * SS + q0) * DD);
#pragma unroll
        for (int i = 0; i < 4; ++i) {
            const int idx = tid + (i << 8);
            const int r = idx >> 3, seg = idx & 7;
            *(uint4*)(sQ + r * ATT_LDH + seg * 8) = qg[r * 8 + seg];
        }
    }
    __syncthreads();

    uint32_t qa[4][4];
    {
        const int r  = wid * 16 + (lane & 15);
        const int c8 = (lane >> 4) * 8;
#pragma unroll
        for (int kk = 0; kk < 4; ++kk) {
            uint32_t a = (uint32_t)__cvta_generic_to_shared(sQ + r * ATT_LDH + kk * 16 + c8);
            LDMATRIX_X4(qa[kk], a);
        }
    }

    float oacc[8][4];
#pragma unroll
    for (int i = 0; i < 8; ++i)
#pragma unroll
        for (int j = 0; j < 4; ++j) oacc[i][j] = 0.f;
    float m0r = -1e30f, m1r = -1e30f, l0 = 0.f, l1 = 0.f;

    for (int t = 0; t < nTiles; ++t) {
        const int j0  = t << 6;
        const int buf = t - (t / 3) * 3;   // t % 3

        asm volatile("cp.async.wait_group 1;" ::: "memory");
        __syncthreads();   // buffer `buf` filled & visible; all warps past t-1

        // keep exactly one commit per iteration
        if (t + 2 < nTiles) {
            const int nb = (t + 2) - ((t + 2) / 3) * 3;
            issue_kv(j0 + 128, nb);
        } else {
            asm volatile("cp.async.commit_group;" ::: "memory");
        }

        const __half* sK = sK0 + buf * (64 * ATT_LDH);
        const __half* sV = sV0 + buf * (64 * ATT_LDH);

        float sacc[8][4];
#pragma unroll
        for (int i = 0; i < 8; ++i)
#pragma unroll
            for (int j = 0; j < 4; ++j) sacc[i][j] = 0.f;

        {
            const int rb = ((lane >> 4) & 1) * 8 + (lane & 7);
            const int cb = ((lane >> 3) & 1) * 8;
#pragma unroll
            for (int kk = 0; kk < 4; ++kk) {
#pragma unroll
                for (int jc = 0; jc < 8; jc += 2) {
                    uint32_t kb[4];
                    uint32_t a = (uint32_t)__cvta_generic_to_shared(
                        sK + (jc * 8 + rb) * ATT_LDH + kk * 16 + cb);
                    LDMATRIX_X4(kb, a);
                    MMA16816(sacc[jc],     qa[kk], kb);
                    MMA16816(sacc[jc + 1], qa[kk], kb + 2);
                }
            }
        }

        const int nk = min(64, len - j0);
        if (nk < 64) {
#pragma unroll
            for (int jc = 0; jc < 8; ++jc) {
                const int c = jc * 8 + t4 * 2;
                if (c     >= nk) { sacc[jc][0] = -1e30f; sacc[jc][2] = -1e30f; }
                if (c + 1 >= nk) { sacc[jc][1] = -1e30f; sacc[jc][3] = -1e30f; }
            }
        }
        float mt0 = -1e30f, mt1 = -1e30f;
#pragma unroll
        for (int jc = 0; jc < 8; ++jc) {
            mt0 = fmaxf(mt0, fmaxf(sacc[jc][0], sacc[jc][1]));
            mt1 = fmaxf(mt1, fmaxf(sacc[jc][2], sacc[jc][3]));
        }
        mt0 = fmaxf(mt0, __shfl_xor_sync(0xffffffffu, mt0, 1));
        mt0 = fmaxf(mt0, __shfl_xor_sync(0xffffffffu, mt0, 2));
        mt1 = fmaxf(mt1, __shfl_xor_sync(0xffffffffu, mt1, 1));
        mt1 = fmaxf(mt1, __shfl_xor_sync(0xffffffffu, mt1, 2));

        const float mn0 = fmaxf(m0r, mt0), mn1 = fmaxf(m1r, mt1);
        const float corr0 = exp2f(m0r - mn0), corr1 = exp2f(m1r - mn1);
        m0r = mn0; m1r = mn1;

        float ls0 = 0.f, ls1 = 0.f;
#pragma unroll
        for (int jc = 0; jc < 8; ++jc) {
            sacc[jc][0] = exp2f(sacc[jc][0] - mn0);
            sacc[jc][1] = exp2f(sacc[jc][1] - mn0);
            sacc[jc][2] = exp2f(sacc[jc][2] - mn1);
            sacc[jc][3] = exp2f(sacc[jc][3] - mn1);
            ls0 += sacc[jc][0] + sacc[jc][1];
            ls1 += sacc[jc][2] + sacc[jc][3];
        }
        ls0 += __shfl_xor_sync(0xffffffffu, ls0, 1);
        ls0 += __shfl_xor_sync(0xffffffffu, ls0, 2);
        ls1 += __shfl_xor_sync(0xffffffffu, ls1, 1);
        ls1 += __shfl_xor_sync(0xffffffffu, ls1, 2);
        l0 = l0 * corr0 + ls0;
        l1 = l1 * corr1 + ls1;

#pragma unroll
        for (int nc = 0; nc < 8; ++nc) {
            oacc[nc][0] *= corr0; oacc[nc][1] *= corr0;
            oacc[nc][2] *= corr1; oacc[nc][3] *= corr1;
        }

        {
            const int rb = ((lane >> 3) & 1) * 8 + (lane & 7);
            const int cb = (lane >> 4) * 8;
#pragma unroll
            for (int kk = 0; kk < 4; ++kk) {
                uint32_t pa[4];
                pa[0] = packh2(sacc[2 * kk][0],     sacc[2 * kk][1]);
                pa[1] = packh2(sacc[2 * kk][2],     sacc[2 * kk][3]);
                pa[2] = packh2(sacc[2 * kk + 1][0], sacc[2 * kk + 1][1]);
                pa[3] = packh2(sacc[2 * kk + 1][2], sacc[2 * kk + 1][3]);
#pragma unroll
                for (int nc = 0; nc < 8; nc += 2) {
                    uint32_t vb[4];
                    uint32_t a = (uint32_t)__cvta_generic_to_shared(
                        sV + (kk * 16 + rb) * ATT_LDH + nc * 8 + cb);
                    LDMATRIX_X4_T(vb, a);
                    MMA16816(oacc[nc],     pa, vb);
                    MMA16816(oacc[nc + 1], pa, vb + 2);
                }
            }
        }
        // no trailing sync: next iteration's barrier protects buffer reuse
    }

    const int qrow0 = q0 + wid * 16 + gid;
    const float fin0 = (qrow0     < len) ? (1.0f / l0) : 0.f;
    const float fin1 = (qrow0 + 8 < len) ? (1.0f / l1) : 0.f;
    __half* base0 = ctxh + ((size_t)bb * SS + qrow0) * EE + hh * DD;
    __half* base1 = base0 + (size_t)8 * EE;
#pragma unroll
    for (int nc = 0; nc < 8; ++nc) {
        const int d = nc * 8 + t4 * 2;
        *(__half2*)(base0 + d) = __floats2half2_rn(oacc[nc][0] * fin0, oacc[nc][1] * fin0);
        *(__half2*)(base1 + d) = __floats2half2_rn(oacc[nc][2] * fin1, oacc[nc][3] * fin1);
    }
}

// ---------------------------------------------------------------------------
// Launch
// ---------------------------------------------------------------------------
extern "C" void kernel_launch(void* const* d_in, const int* in_sizes, int n_in,
                              void* d_out, int out_size)
{
    const float* x            = (const float*)d_in[0];
    const unsigned char* mask = (const unsigned char*)d_in[1];
    const float* Wqkv_w       = (const float*)d_in[2];
    const float* Wqkv_b       = (const float*)d_in[3];
    const float* out_w        = (const float*)d_in[4];
    const float* out_b        = (const float*)d_in[5];
    float* out                = (float*)d_out;

    __half *xh, *wqkvh, *owh, *qh, *kh, *vh, *ctxh;
    cudaGetSymbolAddress((void**)&xh,    g_xh);
    cudaGetSymbolAddress((void**)&wqkvh, g_wqkvh);
    cudaGetSymbolAddress((void**)&owh,   g_owh);
    cudaGetSymbolAddress((void**)&qh,    g_qh);
    cudaGetSymbolAddress((void**)&kh,    g_kh);
    cudaGetSymbolAddress((void**)&vh,    g_vh);
    cudaGetSymbolAddress((void**)&ctxh,  g_ctxh);

    // 1) lengths + fused fp16 conversion (one launch)
    lengths_kernel<<<BB, 32>>>(mask);
    conv_all<<<(CN1 + CN2 + CN3 + 255) / 256, 256>>>(x, Wqkv_w, out_w);

    // 2) QKV projection (mma.sync + cp.async + padded-slab skip)
    cudaFuncSetAttribute(tc_gemm<0>, cudaFuncAttributeMaxDynamicSharedMemorySize, GEMM_SMEM_BYTES);
    cudaFuncSetAttribute(tc_gemm<1>, cudaFuncAttributeMaxDynamicSharedMemorySize, GEMM_SMEM_BYTES);
    {
        dim3 grid(3 * EE / BN, (BB * SS) / BM);
        tc_gemm<0><<<grid, 256, GEMM_SMEM_BYTES>>>(xh, wqkvh, Wqkv_b, nullptr, qh, kh, vh);
    }

    // 3) flash attention (3-stage ring, 2 CTAs/SM) -> ctx fp16
    cudaFuncSetAttribute(attn_kernel, cudaFuncAttributeMaxDynamicSharedMemorySize, ATT_SMEM_BYTES);
    attn_kernel<<<dim3(SS / 128, HH, BB), 256, ATT_SMEM_BYTES>>>(qh, kh, vh, ctxh);

    // 4) output projection (mma.sync + bias-fill for padded slabs)
    {
        dim3 grid(EE / BN, (BB * SS) / BM);
        tc_gemm<1><<<grid, 256, GEMM_SMEM_BYTES>>>(ctxh, owh, out_b, out, nullptr, nullptr, nullptr);
    }
}